// round 7
// baseline (speedup 1.0000x reference)
#include <cuda_runtime.h>
#include <math.h>

#define Bq 2
#define Nn 8192
#define Cc 256
#define Kk 16
#define Dd 32
#define BN_INV 0.99999500003749969f

// ---- scratch (no cudaMalloc allowed) ----
__device__ float g_q[Bq * Nn * Cc];   // [b][n][c] point-major
__device__ float g_k[Bq * Nn * Cc];
__device__ float g_v[Bq * Nn * Cc];
__device__ int   g_idx[Bq * Nn * Kk];

// ============================================================
// exact fp32 helpers (branch-free; all rn intrinsics so neither
// nvcc nor ptxas can contract/reassociate them away)
// ============================================================
__device__ __forceinline__ float2 two_sum(float a, float b) {
    float s  = __fadd_rn(a, b);
    float bp = __fsub_rn(s, a);
    float e  = __fadd_rn(__fsub_rn(a, __fsub_rn(s, bp)), __fsub_rn(b, bp));
    return make_float2(s, e);
}
__device__ __forceinline__ float2 two_prod(float a, float b) {
    float p = __fmul_rn(a, b);
    float e = __fmaf_rn(a, b, -p);
    return make_float2(p, e);
}

// ============================================================
// Kernel 1: QKV 1x1 conv as tiled SGEMM
// ============================================================
#define GM_BM 128
#define GM_BN 64
#define GM_BK 16

__global__ __launch_bounds__(256) void qkv_kernel(
    const float* __restrict__ feat,
    const float* __restrict__ Wq, const float* __restrict__ bq,
    const float* __restrict__ Wk, const float* __restrict__ bk,
    const float* __restrict__ Wv, const float* __restrict__ bv)
{
    int zb = blockIdx.z;
    int b = zb / 3, mat = zb % 3;
    const float* W    = (mat == 0) ? Wq : (mat == 1) ? Wk : Wv;
    const float* bias = (mat == 0) ? bq : (mat == 1) ? bk : bv;
    float* out        = (mat == 0) ? g_q : (mat == 1) ? g_k : g_v;

    int n0 = blockIdx.x * GM_BM;
    int o0 = blockIdx.y * GM_BN;

    __shared__ __align__(16) float As[GM_BK][GM_BM];
    __shared__ float Bs[GM_BK][GM_BN + 1];

    const float* fb = feat + (size_t)b * Cc * Nn;
    int tid = threadIdx.x;
    int ty = tid >> 4;
    int tx = tid & 15;

    float acc[8][4];
#pragma unroll
    for (int i = 0; i < 8; i++)
#pragma unroll
        for (int j = 0; j < 4; j++) acc[i][j] = 0.f;

    for (int c0 = 0; c0 < Cc; c0 += GM_BK) {
        {
            int r = tid >> 4;
            int col = (tid & 15) * 8;
            const float* src = fb + (size_t)(c0 + r) * Nn + n0 + col;
            float4 v0 = *(const float4*)(src);
            float4 v1 = *(const float4*)(src + 4);
            *(float4*)&As[r][col]     = v0;
            *(float4*)&As[r][col + 4] = v1;
        }
        {
            int oo  = tid >> 2;
            int kc4 = (tid & 3) * 4;
            const float* src = W + (size_t)(o0 + oo) * Cc + c0 + kc4;
            float4 v = *(const float4*)src;
            Bs[kc4 + 0][oo] = v.x;
            Bs[kc4 + 1][oo] = v.y;
            Bs[kc4 + 2][oo] = v.z;
            Bs[kc4 + 3][oo] = v.w;
        }
        __syncthreads();
#pragma unroll
        for (int kc = 0; kc < GM_BK; kc++) {
            float a[8], bb[4];
#pragma unroll
            for (int i = 0; i < 8; i++) a[i] = As[kc][ty * 8 + i];
#pragma unroll
            for (int j = 0; j < 4; j++) bb[j] = Bs[kc][tx * 4 + j];
#pragma unroll
            for (int i = 0; i < 8; i++)
#pragma unroll
                for (int j = 0; j < 4; j++)
                    acc[i][j] = fmaf(a[i], bb[j], acc[i][j]);
        }
        __syncthreads();
    }

    float* ob = out + (size_t)b * Nn * Cc;
    float4 bv4 = *(const float4*)(bias + o0 + tx * 4);
#pragma unroll
    for (int i = 0; i < 8; i++) {
        int n = n0 + ty * 8 + i;
        float4 r;
        r.x = fmaxf(acc[i][0] + bv4.x, 0.f);
        r.y = fmaxf(acc[i][1] + bv4.y, 0.f);
        r.z = fmaxf(acc[i][2] + bv4.z, 0.f);
        r.w = fmaxf(acc[i][3] + bv4.w, 0.f);
        *(float4*)&ob[(size_t)n * Cc + o0 + tx * 4] = r;
    }
}

// ============================================================
// Kernel 2: KNN, scheme-agnostic:
//   dot  = fma(qz,cz, fma(qy,cy, rn(qx*cx)))   (universal backend form)
//   sq   = EXACT (float-float)                 (center of scheme cloud)
//   d2   = EXACT combine sqn + sqm - 2*dot     (Sterbenz => matches both
//                                               std and Z associations
//                                               to within ~1 rounding)
// Exact path gated by conservative fp32 filter (margin 1e-5 >> 3e-7).
// ============================================================
#define KNN_TPB 128
#define KNN_TILE 256

__global__ __launch_bounds__(KNN_TPB) void knn_kernel(const float* __restrict__ xyz)
{
    int b = blockIdx.y;
    int n = blockIdx.x * KNN_TPB + threadIdx.x;
    const float* xb = xyz + (size_t)b * Nn * 3;

    float qx = xb[n * 3 + 0], qy = xb[n * 3 + 1], qz = xb[n * 3 + 2];

    // exact query squared norm (hi, lo)
    float sqn_hi, sqn_lo;
    {
        float2 q0 = two_prod(qx, qx), q1 = two_prod(qy, qy), q2 = two_prod(qz, qz);
        float2 s01 = two_sum(q0.x, q1.x);
        float2 s   = two_sum(s01.x, q2.x);
        sqn_hi = s.x;
        sqn_lo = s01.y + s.y + q0.y + q1.y + q2.y;
    }

    float bd[Kk];
    int   bi[Kk];
#pragma unroll
    for (int i = 0; i < Kk; i++) { bd[i] = 3.4e38f; bi[i] = 0; }

    __shared__ float4 tile[KNN_TILE];   // x, y, z, sq_hi
    __shared__ float  tlo[KNN_TILE];    // sq_lo

    for (int m0 = 0; m0 < Nn; m0 += KNN_TILE) {
        __syncthreads();
        for (int j = threadIdx.x; j < KNN_TILE; j += KNN_TPB) {
            float x = xb[(m0 + j) * 3 + 0];
            float y = xb[(m0 + j) * 3 + 1];
            float z = xb[(m0 + j) * 3 + 2];
            float2 p0 = two_prod(x, x), p1 = two_prod(y, y), p2 = two_prod(z, z);
            float2 s01 = two_sum(p0.x, p1.x);
            float2 s   = two_sum(s01.x, p2.x);
            tile[j] = make_float4(x, y, z, s.x);
            tlo[j]  = s01.y + s.y + p0.y + p1.y + p2.y;
        }
        __syncthreads();
#pragma unroll 4
        for (int j = 0; j < KNN_TILE; j++) {
            float4 cpt = tile[j];
            // the one fp32 rounding we deliberately keep: ascending-fma dot
            float dot = __fmaf_rn(qz, cpt.z,
                        __fmaf_rn(qy, cpt.y,
                        __fmul_rn(qx, cpt.x)));
            float m2dot = __fadd_rn(dot, dot);
            // cheap conservative filter (error <= ~3e-7 << 1e-5 margin)
            float cheap = __fsub_rn(__fadd_rn(sqn_hi, cpt.w), m2dot);
            if (cheap < bd[Kk - 1] + 1e-5f) {
                // exact combine: sqn_ff + sqm_ff - 2*dot  (2*dot exact)
                float2 u1 = two_sum(sqn_hi, cpt.w);
                float2 u2 = two_sum(u1.x, -m2dot);
                float d2 = u2.x + (((u1.y + u2.y) + sqn_lo) + tlo[j]);
                if (d2 < bd[Kk - 1]) {
                    float v = d2;
                    int ii = m0 + j;
#pragma unroll
                    for (int i = 0; i < Kk; i++) {
                        if (v < bd[i]) {
                            float tv = bd[i]; int ti = bi[i];
                            bd[i] = v; bi[i] = ii;
                            v = tv; ii = ti;
                        }
                    }
                }
            }
        }
    }

    int* op = g_idx + ((size_t)(b * Nn) + n) * Kk;
#pragma unroll
    for (int i = 0; i < Kk; i++) op[i] = bi[i];
}

// ============================================================
// Kernel 3: fused per-point attention (unchanged)
// ============================================================
__global__ __launch_bounds__(256, 3) void fused_kernel(
    const float* __restrict__ xyz,
    const float* __restrict__ Wp1, const float* __restrict__ bp1,
    const float* __restrict__ g1,  const float* __restrict__ b1,
    const float* __restrict__ Wp2, const float* __restrict__ bp2,
    const float* __restrict__ g0,  const float* __restrict__ b0,
    const float* __restrict__ Ww1, const float* __restrict__ bw1,
    const float* __restrict__ g2,  const float* __restrict__ b2,
    const float* __restrict__ Ww2, const float* __restrict__ bw2,
    float* __restrict__ out)
{
    int bx = blockIdx.x;
    int b = bx >> 13;
    int n = bx & (Nn - 1);
    int tid = threadIdx.x;
    int c = tid;
    int d8 = tid >> 3;
    int r8 = tid & 7;

    __shared__ __align__(16) float wv_s[Cc];
    __shared__ float w_s[Kk][Dd];
    __shared__ float w1_s[Dd];
    __shared__ float w2t_s[Dd * Dd];
    __shared__ float ts_s[3];
    __shared__ int   idx_s[Kk];

    for (int i = tid; i < Dd * Dd; i += 256)
        w2t_s[i] = Ww2[(i & 31) * Dd + (i >> 5)];
    if (tid < Kk) idx_s[tid] = g_idx[((size_t)(b * Nn) + n) * Kk + tid];

    float xqc  = g_q[((size_t)(b * Nn) + n) * Cc + c];
    float wp20 = Wp2[c * 3 + 0], wp21 = Wp2[c * 3 + 1], wp22 = Wp2[c * 3 + 2];
    float bp2c = bp2[c];
    float s0c = g0[c] * BN_INV, h0c = b0[c];
    float bw1d = bw1[d8], s2d = g2[d8] * BN_INV, h2d = b2[d8];
    float bw2r = (tid < Dd) ? bw2[tid] : 0.0f;

    float w1w[32];
#pragma unroll
    for (int j = 0; j < 8; j++) {
        float4 t = *(const float4*)(Ww1 + (size_t)d8 * Cc + j * 32 + r8 * 4);
        w1w[j * 4 + 0] = t.x; w1w[j * 4 + 1] = t.y;
        w1w[j * 4 + 2] = t.z; w1w[j * 4 + 3] = t.w;
    }

    float vreg[Kk];

    __syncthreads();

    for (int kk = 0; kk < Kk; kk++) {
        int m = idx_s[kk];
        if (tid == 0) {
            const float* p = xyz + ((size_t)(b * Nn) + m) * 3;
            float p0 = p[0], p1 = p[1], p2 = p[2];
#pragma unroll
            for (int o = 0; o < 3; o++) {
                float u = Wp1[o * 3 + 0] * p0 + Wp1[o * 3 + 1] * p1
                        + Wp1[o * 3 + 2] * p2 + bp1[o];
                u = u * (g1[o] * BN_INV) + b1[o];
                ts_s[o] = fmaxf(u, 0.f);
            }
        }
        __syncthreads();

        float t0 = ts_s[0], t1 = ts_s[1], t2 = ts_s[2];
        float pr = fmaxf(wp20 * t0 + wp21 * t1 + wp22 * t2 + bp2c, 0.f);
        size_t base = ((size_t)(b * Nn) + m) * Cc + c;
        float xk = g_k[base];
        float xv = g_v[base];
        float wvv = fmaxf((xk - xqc + pr) * s0c + h0c, 0.f);
        wv_s[c] = wvv;
        vreg[kk] = xv + pr;
        __syncthreads();

        float part = 0.f;
#pragma unroll
        for (int j = 0; j < 8; j++) {
            float4 wq = *(const float4*)(wv_s + j * 32 + r8 * 4);
            part = fmaf(w1w[j * 4 + 0], wq.x, part);
            part = fmaf(w1w[j * 4 + 1], wq.y, part);
            part = fmaf(w1w[j * 4 + 2], wq.z, part);
            part = fmaf(w1w[j * 4 + 3], wq.w, part);
        }
        part += __shfl_xor_sync(0xffffffffu, part, 4);
        part += __shfl_xor_sync(0xffffffffu, part, 2);
        part += __shfl_xor_sync(0xffffffffu, part, 1);
        if (r8 == 0) {
            float u = (part + bw1d) * s2d + h2d;
            w1_s[d8] = fmaxf(u, 0.f);
        }
        __syncthreads();

        if (tid < Dd) {
            float acc = bw2r;
#pragma unroll
            for (int dd = 0; dd < Dd; dd++)
                acc = fmaf(w2t_s[dd * Dd + tid], w1_s[dd], acc);
            w_s[kk][tid] = fmaxf(acc, 0.f);
        }
        __syncthreads();
    }

    if (tid < Dd) {
        float mx = -3.4e38f;
#pragma unroll
        for (int kk = 0; kk < Kk; kk++) mx = fmaxf(mx, w_s[kk][tid]);
        float sum = 0.f;
#pragma unroll
        for (int kk = 0; kk < Kk; kk++) {
            float e = expf(w_s[kk][tid] - mx);
            w_s[kk][tid] = e;
            sum += e;
        }
        float rs = 1.0f / sum;
#pragma unroll
        for (int kk = 0; kk < Kk; kk++) w_s[kk][tid] *= rs;
    }
    __syncthreads();

    float acc = 0.f;
    int dd = c & 31;
#pragma unroll
    for (int kk = 0; kk < Kk; kk++)
        acc = fmaf(vreg[kk], w_s[kk][dd], acc);
    out[((size_t)b * Cc + c) * Nn + n] = acc;
}

// ============================================================
// launch
// ============================================================
extern "C" void kernel_launch(void* const* d_in, const int* in_sizes, int n_in,
                              void* d_out, int out_size)
{
    const float* xyz  = (const float*)d_in[0];
    const float* feat = (const float*)d_in[1];
    const float* Wq = (const float*)d_in[2];   const float* bqp = (const float*)d_in[3];
    const float* Wk = (const float*)d_in[4];   const float* bkp = (const float*)d_in[5];
    const float* Wv = (const float*)d_in[6];   const float* bvp = (const float*)d_in[7];
    const float* Wp1 = (const float*)d_in[8];  const float* bp1 = (const float*)d_in[9];
    const float* g1  = (const float*)d_in[10]; const float* b1  = (const float*)d_in[11];
    const float* Wp2 = (const float*)d_in[12]; const float* bp2 = (const float*)d_in[13];
    const float* g0  = (const float*)d_in[14]; const float* b0  = (const float*)d_in[15];
    const float* Ww1 = (const float*)d_in[16]; const float* bw1 = (const float*)d_in[17];
    const float* g2  = (const float*)d_in[18]; const float* b2  = (const float*)d_in[19];
    const float* Ww2 = (const float*)d_in[20]; const float* bw2 = (const float*)d_in[21];
    float* out = (float*)d_out;

    dim3 ggrid(Nn / GM_BM, Cc / GM_BN, 6);
    qkv_kernel<<<ggrid, 256>>>(feat, Wq, bqp, Wk, bkp, Wv, bvp);

    dim3 kgrid(Nn / KNN_TPB, Bq);
    knn_kernel<<<kgrid, KNN_TPB>>>(xyz);

    fused_kernel<<<Bq * Nn, 256>>>(xyz,
                                   Wp1, bp1, g1, b1, Wp2, bp2,
                                   g0, b0, Ww1, bw1, g2, b2, Ww2, bw2,
                                   out);
}

// round 8
// speedup vs baseline: 1.0886x; 1.0886x over previous
#include <cuda_runtime.h>
#include <math.h>

#define Bq 2
#define Nn 8192
#define Cc 256
#define Kk 16
#define Dd 32
#define BN_INV 0.99999500003749969f

// ---- scratch (no cudaMalloc allowed) ----
__device__ float g_q[Bq * Nn * Cc];   // [b][n][c] point-major
__device__ float g_k[Bq * Nn * Cc];
__device__ float g_v[Bq * Nn * Cc];
__device__ int   g_idx[Bq * Nn * Kk];

// ============================================================
// exact fp32 helpers (branch-free; all rn intrinsics so neither
// nvcc nor ptxas can contract/reassociate them away)
// ============================================================
__device__ __forceinline__ float2 two_sum(float a, float b) {
    float s  = __fadd_rn(a, b);
    float bp = __fsub_rn(s, a);
    float e  = __fadd_rn(__fsub_rn(a, __fsub_rn(s, bp)), __fsub_rn(b, bp));
    return make_float2(s, e);
}
__device__ __forceinline__ float2 two_prod(float a, float b) {
    float p = __fmul_rn(a, b);
    float e = __fmaf_rn(a, b, -p);
    return make_float2(p, e);
}

// ============================================================
// Kernel 1: QKV 1x1 conv as tiled SGEMM  (unchanged from R7)
// ============================================================
#define GM_BM 128
#define GM_BN 64
#define GM_BK 16

__global__ __launch_bounds__(256) void qkv_kernel(
    const float* __restrict__ feat,
    const float* __restrict__ Wq, const float* __restrict__ bq,
    const float* __restrict__ Wk, const float* __restrict__ bk,
    const float* __restrict__ Wv, const float* __restrict__ bv)
{
    int zb = blockIdx.z;
    int b = zb / 3, mat = zb % 3;
    const float* W    = (mat == 0) ? Wq : (mat == 1) ? Wk : Wv;
    const float* bias = (mat == 0) ? bq : (mat == 1) ? bk : bv;
    float* out        = (mat == 0) ? g_q : (mat == 1) ? g_k : g_v;

    int n0 = blockIdx.x * GM_BM;
    int o0 = blockIdx.y * GM_BN;

    __shared__ __align__(16) float As[GM_BK][GM_BM];
    __shared__ float Bs[GM_BK][GM_BN + 1];

    const float* fb = feat + (size_t)b * Cc * Nn;
    int tid = threadIdx.x;
    int ty = tid >> 4;
    int tx = tid & 15;

    float acc[8][4];
#pragma unroll
    for (int i = 0; i < 8; i++)
#pragma unroll
        for (int j = 0; j < 4; j++) acc[i][j] = 0.f;

    for (int c0 = 0; c0 < Cc; c0 += GM_BK) {
        {
            int r = tid >> 4;
            int col = (tid & 15) * 8;
            const float* src = fb + (size_t)(c0 + r) * Nn + n0 + col;
            float4 v0 = *(const float4*)(src);
            float4 v1 = *(const float4*)(src + 4);
            *(float4*)&As[r][col]     = v0;
            *(float4*)&As[r][col + 4] = v1;
        }
        {
            int oo  = tid >> 2;
            int kc4 = (tid & 3) * 4;
            const float* src = W + (size_t)(o0 + oo) * Cc + c0 + kc4;
            float4 v = *(const float4*)src;
            Bs[kc4 + 0][oo] = v.x;
            Bs[kc4 + 1][oo] = v.y;
            Bs[kc4 + 2][oo] = v.z;
            Bs[kc4 + 3][oo] = v.w;
        }
        __syncthreads();
#pragma unroll
        for (int kc = 0; kc < GM_BK; kc++) {
            float a[8], bb[4];
#pragma unroll
            for (int i = 0; i < 8; i++) a[i] = As[kc][ty * 8 + i];
#pragma unroll
            for (int j = 0; j < 4; j++) bb[j] = Bs[kc][tx * 4 + j];
#pragma unroll
            for (int i = 0; i < 8; i++)
#pragma unroll
                for (int j = 0; j < 4; j++)
                    acc[i][j] = fmaf(a[i], bb[j], acc[i][j]);
        }
        __syncthreads();
    }

    float* ob = out + (size_t)b * Nn * Cc;
    float4 bv4 = *(const float4*)(bias + o0 + tx * 4);
#pragma unroll
    for (int i = 0; i < 8; i++) {
        int n = n0 + ty * 8 + i;
        float4 r;
        r.x = fmaxf(acc[i][0] + bv4.x, 0.f);
        r.y = fmaxf(acc[i][1] + bv4.y, 0.f);
        r.z = fmaxf(acc[i][2] + bv4.z, 0.f);
        r.w = fmaxf(acc[i][3] + bv4.w, 0.f);
        *(float4*)&ob[(size_t)n * Cc + o0 + tx * 4] = r;
    }
}

// ============================================================
// Kernel 2: KNN  (FROZEN — byte-identical to the passing R7)
// ============================================================
#define KNN_TPB 128
#define KNN_TILE 256

__global__ __launch_bounds__(KNN_TPB) void knn_kernel(const float* __restrict__ xyz)
{
    int b = blockIdx.y;
    int n = blockIdx.x * KNN_TPB + threadIdx.x;
    const float* xb = xyz + (size_t)b * Nn * 3;

    float qx = xb[n * 3 + 0], qy = xb[n * 3 + 1], qz = xb[n * 3 + 2];

    float sqn_hi, sqn_lo;
    {
        float2 q0 = two_prod(qx, qx), q1 = two_prod(qy, qy), q2 = two_prod(qz, qz);
        float2 s01 = two_sum(q0.x, q1.x);
        float2 s   = two_sum(s01.x, q2.x);
        sqn_hi = s.x;
        sqn_lo = s01.y + s.y + q0.y + q1.y + q2.y;
    }

    float bd[Kk];
    int   bi[Kk];
#pragma unroll
    for (int i = 0; i < Kk; i++) { bd[i] = 3.4e38f; bi[i] = 0; }

    __shared__ float4 tile[KNN_TILE];
    __shared__ float  tlo[KNN_TILE];

    for (int m0 = 0; m0 < Nn; m0 += KNN_TILE) {
        __syncthreads();
        for (int j = threadIdx.x; j < KNN_TILE; j += KNN_TPB) {
            float x = xb[(m0 + j) * 3 + 0];
            float y = xb[(m0 + j) * 3 + 1];
            float z = xb[(m0 + j) * 3 + 2];
            float2 p0 = two_prod(x, x), p1 = two_prod(y, y), p2 = two_prod(z, z);
            float2 s01 = two_sum(p0.x, p1.x);
            float2 s   = two_sum(s01.x, p2.x);
            tile[j] = make_float4(x, y, z, s.x);
            tlo[j]  = s01.y + s.y + p0.y + p1.y + p2.y;
        }
        __syncthreads();
#pragma unroll 4
        for (int j = 0; j < KNN_TILE; j++) {
            float4 cpt = tile[j];
            float dot = __fmaf_rn(qz, cpt.z,
                        __fmaf_rn(qy, cpt.y,
                        __fmul_rn(qx, cpt.x)));
            float m2dot = __fadd_rn(dot, dot);
            float cheap = __fsub_rn(__fadd_rn(sqn_hi, cpt.w), m2dot);
            if (cheap < bd[Kk - 1] + 1e-5f) {
                float2 u1 = two_sum(sqn_hi, cpt.w);
                float2 u2 = two_sum(u1.x, -m2dot);
                float d2 = u2.x + (((u1.y + u2.y) + sqn_lo) + tlo[j]);
                if (d2 < bd[Kk - 1]) {
                    float v = d2;
                    int ii = m0 + j;
#pragma unroll
                    for (int i = 0; i < Kk; i++) {
                        if (v < bd[i]) {
                            float tv = bd[i]; int ti = bi[i];
                            bd[i] = v; bi[i] = ii;
                            v = tv; ii = ti;
                        }
                    }
                }
            }
        }
    }

    int* op = g_idx + ((size_t)(b * Nn) + n) * Kk;
#pragma unroll
    for (int i = 0; i < Kk; i++) op[i] = bi[i];
}

// ============================================================
// Kernel 3: fused per-point attention — RESTRUCTURED
// All 16 neighbors processed phase-parallel; 6 barriers total
// (was 64+). Every float expression / reduction order preserved
// from the passing R7 kernel => bit-identical output.
// ============================================================
__global__ __launch_bounds__(256, 2) void fused_kernel(
    const float* __restrict__ xyz,
    const float* __restrict__ Wp1, const float* __restrict__ bp1,
    const float* __restrict__ g1,  const float* __restrict__ b1,
    const float* __restrict__ Wp2, const float* __restrict__ bp2,
    const float* __restrict__ g0,  const float* __restrict__ b0,
    const float* __restrict__ Ww1, const float* __restrict__ bw1,
    const float* __restrict__ g2,  const float* __restrict__ b2,
    const float* __restrict__ Ww2, const float* __restrict__ bw2,
    float* __restrict__ out)
{
    int bx = blockIdx.x;
    int b = bx >> 13;
    int n = bx & (Nn - 1);
    int tid = threadIdx.x;
    int c = tid;
    int d8 = tid >> 3;
    int r8 = tid & 7;

    __shared__ __align__(16) float wv_s[Kk][Cc];   // 16 KB
    __shared__ float w1_all[Kk][Dd];
    __shared__ float w_s[Kk][Dd];
    __shared__ float w2t_s[Dd * Dd];
    __shared__ float ts_s[Kk][3];
    __shared__ int   idx_s[Kk];

    // ---- setup ----
    for (int i = tid; i < Dd * Dd; i += 256)
        w2t_s[i] = Ww2[(i & 31) * Dd + (i >> 5)];
    if (tid < Kk) idx_s[tid] = g_idx[((size_t)(b * Nn) + n) * Kk + tid];

    float xqc  = g_q[((size_t)(b * Nn) + n) * Cc + c];
    float wp20 = Wp2[c * 3 + 0], wp21 = Wp2[c * 3 + 1], wp22 = Wp2[c * 3 + 2];
    float bp2c = bp2[c];
    float s0c = g0[c] * BN_INV, h0c = b0[c];
    float bw1d = bw1[d8], s2d = g2[d8] * BN_INV, h2d = b2[d8];
    float bw2r = bw2[tid & 31];

    float w1w[32];
#pragma unroll
    for (int j = 0; j < 8; j++) {
        float4 t = *(const float4*)(Ww1 + (size_t)d8 * Cc + j * 32 + r8 * 4);
        w1w[j * 4 + 0] = t.x; w1w[j * 4 + 1] = t.y;
        w1w[j * 4 + 2] = t.z; w1w[j * 4 + 3] = t.w;
    }
    __syncthreads();   // idx_s, w2t_s ready

    // ---- phase 1: ts for all 16 neighbors in parallel (48 threads) ----
    if (tid < Kk * 3) {
        int k = tid / 3, o = tid % 3;
        int m = idx_s[k];
        const float* p = xyz + ((size_t)(b * Nn) + m) * 3;
        float p0 = p[0], p1 = p[1], p2 = p[2];
        float u = Wp1[o * 3 + 0] * p0 + Wp1[o * 3 + 1] * p1
                + Wp1[o * 3 + 2] * p2 + bp1[o];
        u = u * (g1[o] * BN_INV) + b1[o];
        ts_s[k][o] = fmaxf(u, 0.f);
    }
    __syncthreads();

    // ---- phase 2: pr / wv / v for all neighbors (batched gathers) ----
    float vreg[Kk];
#pragma unroll
    for (int kk = 0; kk < Kk; kk++) {
        int m = idx_s[kk];
        float t0 = ts_s[kk][0], t1 = ts_s[kk][1], t2 = ts_s[kk][2];
        float pr = fmaxf(wp20 * t0 + wp21 * t1 + wp22 * t2 + bp2c, 0.f);
        size_t base = ((size_t)(b * Nn) + m) * Cc + c;
        float xk = g_k[base];
        float xv = g_v[base];
        wv_s[kk][c] = fmaxf((xk - xqc + pr) * s0c + h0c, 0.f);
        vreg[kk] = xv + pr;
    }
    __syncthreads();

    // ---- phase 3: w1 GEMV for all k, no inner barriers ----
#pragma unroll
    for (int kk = 0; kk < Kk; kk++) {
        float part = 0.f;
#pragma unroll
        for (int j = 0; j < 8; j++) {
            float4 wq = *(const float4*)(&wv_s[kk][j * 32 + r8 * 4]);
            part = fmaf(w1w[j * 4 + 0], wq.x, part);
            part = fmaf(w1w[j * 4 + 1], wq.y, part);
            part = fmaf(w1w[j * 4 + 2], wq.z, part);
            part = fmaf(w1w[j * 4 + 3], wq.w, part);
        }
        part += __shfl_xor_sync(0xffffffffu, part, 4);
        part += __shfl_xor_sync(0xffffffffu, part, 2);
        part += __shfl_xor_sync(0xffffffffu, part, 1);
        if (r8 == 0) {
            float u = (part + bw1d) * s2d + h2d;
            w1_all[kk][d8] = fmaxf(u, 0.f);
        }
    }
    __syncthreads();

    // ---- phase 4: w2 — 512 outputs, 2 per thread, same dd order ----
#pragma unroll
    for (int r = 0; r < 2; r++) {
        int oidx = tid + r * 256;
        int k = oidx >> 5, e = oidx & 31;
        float acc = bw2r;
#pragma unroll
        for (int dd = 0; dd < Dd; dd++)
            acc = fmaf(w2t_s[dd * Dd + e], w1_all[k][dd], acc);
        w_s[k][e] = fmaxf(acc, 0.f);
    }
    __syncthreads();

    // ---- softmax over K per channel e (unchanged) ----
    if (tid < Dd) {
        float mx = -3.4e38f;
#pragma unroll
        for (int kk = 0; kk < Kk; kk++) mx = fmaxf(mx, w_s[kk][tid]);
        float sum = 0.f;
#pragma unroll
        for (int kk = 0; kk < Kk; kk++) {
            float e = expf(w_s[kk][tid] - mx);
            w_s[kk][tid] = e;
            sum += e;
        }
        float rs = 1.0f / sum;
#pragma unroll
        for (int kk = 0; kk < Kk; kk++) w_s[kk][tid] *= rs;
    }
    __syncthreads();

    // ---- weighted neighbor reduction (unchanged) ----
    float acc = 0.f;
    int dd = c & 31;
#pragma unroll
    for (int kk = 0; kk < Kk; kk++)
        acc = fmaf(vreg[kk], w_s[kk][dd], acc);
    out[((size_t)b * Cc + c) * Nn + n] = acc;
}

// ============================================================
// launch
// ============================================================
extern "C" void kernel_launch(void* const* d_in, const int* in_sizes, int n_in,
                              void* d_out, int out_size)
{
    const float* xyz  = (const float*)d_in[0];
    const float* feat = (const float*)d_in[1];
    const float* Wq = (const float*)d_in[2];   const float* bqp = (const float*)d_in[3];
    const float* Wk = (const float*)d_in[4];   const float* bkp = (const float*)d_in[5];
    const float* Wv = (const float*)d_in[6];   const float* bvp = (const float*)d_in[7];
    const float* Wp1 = (const float*)d_in[8];  const float* bp1 = (const float*)d_in[9];
    const float* g1  = (const float*)d_in[10]; const float* b1  = (const float*)d_in[11];
    const float* Wp2 = (const float*)d_in[12]; const float* bp2 = (const float*)d_in[13];
    const float* g0  = (const float*)d_in[14]; const float* b0  = (const float*)d_in[15];
    const float* Ww1 = (const float*)d_in[16]; const float* bw1 = (const float*)d_in[17];
    const float* g2  = (const float*)d_in[18]; const float* b2  = (const float*)d_in[19];
    const float* Ww2 = (const float*)d_in[20]; const float* bw2 = (const float*)d_in[21];
    float* out = (float*)d_out;

    dim3 ggrid(Nn / GM_BM, Cc / GM_BN, 6);
    qkv_kernel<<<ggrid, 256>>>(feat, Wq, bqp, Wk, bkp, Wv, bvp);

    dim3 kgrid(Nn / KNN_TPB, Bq);
    knn_kernel<<<kgrid, KNN_TPB>>>(xyz);

    fused_kernel<<<Bq * Nn, 256>>>(xyz,
                                   Wp1, bp1, g1, b1, Wp2, bp2,
                                   g0, b0, Ww1, bw1, g2, b2, Ww2, bw2,
                                   out);
}

// round 9
// speedup vs baseline: 1.3527x; 1.2426x over previous
#include <cuda_runtime.h>
#include <math.h>

#define Bq 2
#define Nn 8192
#define Cc 256
#define Kk 16
#define Dd 32
#define NR 4            // KNN candidate ranges
#define RANGE (Nn / NR) // 2048
#define BN_INV 0.99999500003749969f

// ---- scratch (no cudaMalloc allowed) ----
__device__ float g_q[Bq * Nn * Cc];   // [b][n][c] point-major
__device__ float g_k[Bq * Nn * Cc];
__device__ float g_v[Bq * Nn * Cc];
__device__ int   g_idx[Bq * Nn * Kk];
__device__ float g_pd[Bq * Nn * NR * Kk];   // partial top-16 d2
__device__ int   g_pi[Bq * Nn * NR * Kk];   // partial top-16 idx

// ============================================================
// exact fp32 helpers
// ============================================================
__device__ __forceinline__ float2 two_sum(float a, float b) {
    float s  = __fadd_rn(a, b);
    float bp = __fsub_rn(s, a);
    float e  = __fadd_rn(__fsub_rn(a, __fsub_rn(s, bp)), __fsub_rn(b, bp));
    return make_float2(s, e);
}
__device__ __forceinline__ float2 two_prod(float a, float b) {
    float p = __fmul_rn(a, b);
    float e = __fmaf_rn(a, b, -p);
    return make_float2(p, e);
}

// ============================================================
// Kernel 1: QKV 1x1 conv as tiled SGEMM (unchanged)
// ============================================================
#define GM_BM 128
#define GM_BN 64
#define GM_BK 16

__global__ __launch_bounds__(256) void qkv_kernel(
    const float* __restrict__ feat,
    const float* __restrict__ Wq, const float* __restrict__ bq,
    const float* __restrict__ Wk, const float* __restrict__ bk,
    const float* __restrict__ Wv, const float* __restrict__ bv)
{
    int zb = blockIdx.z;
    int b = zb / 3, mat = zb % 3;
    const float* W    = (mat == 0) ? Wq : (mat == 1) ? Wk : Wv;
    const float* bias = (mat == 0) ? bq : (mat == 1) ? bk : bv;
    float* out        = (mat == 0) ? g_q : (mat == 1) ? g_k : g_v;

    int n0 = blockIdx.x * GM_BM;
    int o0 = blockIdx.y * GM_BN;

    __shared__ __align__(16) float As[GM_BK][GM_BM];
    __shared__ float Bs[GM_BK][GM_BN + 1];

    const float* fb = feat + (size_t)b * Cc * Nn;
    int tid = threadIdx.x;
    int ty = tid >> 4;
    int tx = tid & 15;

    float acc[8][4];
#pragma unroll
    for (int i = 0; i < 8; i++)
#pragma unroll
        for (int j = 0; j < 4; j++) acc[i][j] = 0.f;

    for (int c0 = 0; c0 < Cc; c0 += GM_BK) {
        {
            int r = tid >> 4;
            int col = (tid & 15) * 8;
            const float* src = fb + (size_t)(c0 + r) * Nn + n0 + col;
            float4 v0 = *(const float4*)(src);
            float4 v1 = *(const float4*)(src + 4);
            *(float4*)&As[r][col]     = v0;
            *(float4*)&As[r][col + 4] = v1;
        }
        {
            int oo  = tid >> 2;
            int kc4 = (tid & 3) * 4;
            const float* src = W + (size_t)(o0 + oo) * Cc + c0 + kc4;
            float4 v = *(const float4*)src;
            Bs[kc4 + 0][oo] = v.x;
            Bs[kc4 + 1][oo] = v.y;
            Bs[kc4 + 2][oo] = v.z;
            Bs[kc4 + 3][oo] = v.w;
        }
        __syncthreads();
#pragma unroll
        for (int kc = 0; kc < GM_BK; kc++) {
            float a[8], bb[4];
#pragma unroll
            for (int i = 0; i < 8; i++) a[i] = As[kc][ty * 8 + i];
#pragma unroll
            for (int j = 0; j < 4; j++) bb[j] = Bs[kc][tx * 4 + j];
#pragma unroll
            for (int i = 0; i < 8; i++)
#pragma unroll
                for (int j = 0; j < 4; j++)
                    acc[i][j] = fmaf(a[i], bb[j], acc[i][j]);
        }
        __syncthreads();
    }

    float* ob = out + (size_t)b * Nn * Cc;
    float4 bv4 = *(const float4*)(bias + o0 + tx * 4);
#pragma unroll
    for (int i = 0; i < 8; i++) {
        int n = n0 + ty * 8 + i;
        float4 r;
        r.x = fmaxf(acc[i][0] + bv4.x, 0.f);
        r.y = fmaxf(acc[i][1] + bv4.y, 0.f);
        r.z = fmaxf(acc[i][2] + bv4.z, 0.f);
        r.w = fmaxf(acc[i][3] + bv4.w, 0.f);
        *(float4*)&ob[(size_t)n * Cc + o0 + tx * 4] = r;
    }
}

// ============================================================
// Kernel 2a: KNN partial — each block scans ONE candidate range
// per-candidate arithmetic FROZEN (identical to passing R7/R8)
// ============================================================
#define KNN_TPB 128
#define KNN_TILE 256

__global__ __launch_bounds__(KNN_TPB) void knn_part_kernel(const float* __restrict__ xyz)
{
    int b = blockIdx.z;
    int r = blockIdx.y;                 // candidate range
    int n = blockIdx.x * KNN_TPB + threadIdx.x;
    const float* xb = xyz + (size_t)b * Nn * 3;

    float qx = xb[n * 3 + 0], qy = xb[n * 3 + 1], qz = xb[n * 3 + 2];

    float sqn_hi, sqn_lo;
    {
        float2 q0 = two_prod(qx, qx), q1 = two_prod(qy, qy), q2 = two_prod(qz, qz);
        float2 s01 = two_sum(q0.x, q1.x);
        float2 s   = two_sum(s01.x, q2.x);
        sqn_hi = s.x;
        sqn_lo = s01.y + s.y + q0.y + q1.y + q2.y;
    }

    float bd[Kk];
    int   bi[Kk];
#pragma unroll
    for (int i = 0; i < Kk; i++) { bd[i] = 3.4e38f; bi[i] = 0; }

    __shared__ float4 tile[KNN_TILE];
    __shared__ float  tlo[KNN_TILE];

    int mbase = r * RANGE;
    for (int m0 = mbase; m0 < mbase + RANGE; m0 += KNN_TILE) {
        __syncthreads();
        for (int j = threadIdx.x; j < KNN_TILE; j += KNN_TPB) {
            float x = xb[(m0 + j) * 3 + 0];
            float y = xb[(m0 + j) * 3 + 1];
            float z = xb[(m0 + j) * 3 + 2];
            float2 p0 = two_prod(x, x), p1 = two_prod(y, y), p2 = two_prod(z, z);
            float2 s01 = two_sum(p0.x, p1.x);
            float2 s   = two_sum(s01.x, p2.x);
            tile[j] = make_float4(x, y, z, s.x);
            tlo[j]  = s01.y + s.y + p0.y + p1.y + p2.y;
        }
        __syncthreads();
#pragma unroll 4
        for (int j = 0; j < KNN_TILE; j++) {
            float4 cpt = tile[j];
            float dot = __fmaf_rn(qz, cpt.z,
                        __fmaf_rn(qy, cpt.y,
                        __fmul_rn(qx, cpt.x)));
            float m2dot = __fadd_rn(dot, dot);
            float cheap = __fsub_rn(__fadd_rn(sqn_hi, cpt.w), m2dot);
            if (cheap < bd[Kk - 1] + 1e-5f) {
                float2 u1 = two_sum(sqn_hi, cpt.w);
                float2 u2 = two_sum(u1.x, -m2dot);
                float d2 = u2.x + (((u1.y + u2.y) + sqn_lo) + tlo[j]);
                if (d2 < bd[Kk - 1]) {
                    float v = d2;
                    int ii = m0 + j;
#pragma unroll
                    for (int i = 0; i < Kk; i++) {
                        if (v < bd[i]) {
                            float tv = bd[i]; int ti = bi[i];
                            bd[i] = v; bi[i] = ii;
                            v = tv; ii = ti;
                        }
                    }
                }
            }
        }
    }

    size_t o = (((size_t)(b * Nn) + n) * NR + r) * Kk;
#pragma unroll
    for (int i = 0; i < Kk; i++) { g_pd[o + i] = bd[i]; g_pi[o + i] = bi[i]; }
}

// ============================================================
// Kernel 2b: KNN merge — ranges scanned in ascending order, same
// strict-< insertion => identical (d2, idx) order as monolithic
// ============================================================
__global__ __launch_bounds__(KNN_TPB) void knn_merge_kernel()
{
    int b = blockIdx.y;
    int n = blockIdx.x * KNN_TPB + threadIdx.x;

    float bd[Kk];
    int   bi[Kk];
#pragma unroll
    for (int i = 0; i < Kk; i++) { bd[i] = 3.4e38f; bi[i] = 0; }

    size_t base = ((size_t)(b * Nn) + n) * NR * Kk;
    for (int e = 0; e < NR * Kk; e++) {
        float v = g_pd[base + e];
        int  ii = g_pi[base + e];
        if (v < bd[Kk - 1]) {
#pragma unroll
            for (int i = 0; i < Kk; i++) {
                if (v < bd[i]) {
                    float tv = bd[i]; int ti = bi[i];
                    bd[i] = v; bi[i] = ii;
                    v = tv; ii = ti;
                }
            }
        }
    }

    int* op = g_idx + ((size_t)(b * Nn) + n) * Kk;
#pragma unroll
    for (int i = 0; i < Kk; i++) op[i] = bi[i];
}

// ============================================================
// Kernel 3: fused per-point attention (numerics frozen;
// unroll factors trimmed to cut register pressure)
// ============================================================
__global__ __launch_bounds__(256, 2) void fused_kernel(
    const float* __restrict__ xyz,
    const float* __restrict__ Wp1, const float* __restrict__ bp1,
    const float* __restrict__ g1,  const float* __restrict__ b1,
    const float* __restrict__ Wp2, const float* __restrict__ bp2,
    const float* __restrict__ g0,  const float* __restrict__ b0,
    const float* __restrict__ Ww1, const float* __restrict__ bw1,
    const float* __restrict__ g2,  const float* __restrict__ b2,
    const float* __restrict__ Ww2, const float* __restrict__ bw2,
    float* __restrict__ out)
{
    int bx = blockIdx.x;
    int b = bx >> 13;
    int n = bx & (Nn - 1);
    int tid = threadIdx.x;
    int c = tid;
    int d8 = tid >> 3;
    int r8 = tid & 7;

    __shared__ __align__(16) float wv_s[Kk][Cc];
    __shared__ float w1_all[Kk][Dd];
    __shared__ float w_s[Kk][Dd];
    __shared__ float w2t_s[Dd * Dd];
    __shared__ float ts_s[Kk][3];
    __shared__ int   idx_s[Kk];

    for (int i = tid; i < Dd * Dd; i += 256)
        w2t_s[i] = Ww2[(i & 31) * Dd + (i >> 5)];
    if (tid < Kk) idx_s[tid] = g_idx[((size_t)(b * Nn) + n) * Kk + tid];

    float xqc  = g_q[((size_t)(b * Nn) + n) * Cc + c];
    float wp20 = Wp2[c * 3 + 0], wp21 = Wp2[c * 3 + 1], wp22 = Wp2[c * 3 + 2];
    float bp2c = bp2[c];
    float s0c = g0[c] * BN_INV, h0c = b0[c];
    float bw1d = bw1[d8], s2d = g2[d8] * BN_INV, h2d = b2[d8];
    float bw2r = bw2[tid & 31];

    float w1w[32];
#pragma unroll
    for (int j = 0; j < 8; j++) {
        float4 t = *(const float4*)(Ww1 + (size_t)d8 * Cc + j * 32 + r8 * 4);
        w1w[j * 4 + 0] = t.x; w1w[j * 4 + 1] = t.y;
        w1w[j * 4 + 2] = t.z; w1w[j * 4 + 3] = t.w;
    }
    __syncthreads();

    // phase 1: ts for all 16 neighbors (48 threads)
    if (tid < Kk * 3) {
        int k = tid / 3, o = tid % 3;
        int m = idx_s[k];
        const float* p = xyz + ((size_t)(b * Nn) + m) * 3;
        float p0 = p[0], p1 = p[1], p2 = p[2];
        float u = Wp1[o * 3 + 0] * p0 + Wp1[o * 3 + 1] * p1
                + Wp1[o * 3 + 2] * p2 + bp1[o];
        u = u * (g1[o] * BN_INV) + b1[o];
        ts_s[k][o] = fmaxf(u, 0.f);
    }
    __syncthreads();

    // phase 2: pr / wv / v (moderate unroll for reg pressure)
    float vreg[Kk];
#pragma unroll 4
    for (int kk = 0; kk < Kk; kk++) {
        int m = idx_s[kk];
        float t0 = ts_s[kk][0], t1 = ts_s[kk][1], t2 = ts_s[kk][2];
        float pr = fmaxf(wp20 * t0 + wp21 * t1 + wp22 * t2 + bp2c, 0.f);
        size_t base = ((size_t)(b * Nn) + m) * Cc + c;
        float xk = g_k[base];
        float xv = g_v[base];
        wv_s[kk][c] = fmaxf((xk - xqc + pr) * s0c + h0c, 0.f);
        vreg[kk] = xv + pr;
    }
    __syncthreads();

    // phase 3: w1 GEMV for all k
#pragma unroll 4
    for (int kk = 0; kk < Kk; kk++) {
        float part = 0.f;
#pragma unroll
        for (int j = 0; j < 8; j++) {
            float4 wq = *(const float4*)(&wv_s[kk][j * 32 + r8 * 4]);
            part = fmaf(w1w[j * 4 + 0], wq.x, part);
            part = fmaf(w1w[j * 4 + 1], wq.y, part);
            part = fmaf(w1w[j * 4 + 2], wq.z, part);
            part = fmaf(w1w[j * 4 + 3], wq.w, part);
        }
        part += __shfl_xor_sync(0xffffffffu, part, 4);
        part += __shfl_xor_sync(0xffffffffu, part, 2);
        part += __shfl_xor_sync(0xffffffffu, part, 1);
        if (r8 == 0) {
            float u = (part + bw1d) * s2d + h2d;
            w1_all[kk][d8] = fmaxf(u, 0.f);
        }
    }
    __syncthreads();

    // phase 4: w2 — 512 outputs, 2 per thread
#pragma unroll
    for (int r = 0; r < 2; r++) {
        int oidx = tid + r * 256;
        int k = oidx >> 5, e = oidx & 31;
        float acc = bw2r;
#pragma unroll
        for (int dd = 0; dd < Dd; dd++)
            acc = fmaf(w2t_s[dd * Dd + e], w1_all[k][dd], acc);
        w_s[k][e] = fmaxf(acc, 0.f);
    }
    __syncthreads();

    // softmax over K per channel e
    if (tid < Dd) {
        float mx = -3.4e38f;
#pragma unroll
        for (int kk = 0; kk < Kk; kk++) mx = fmaxf(mx, w_s[kk][tid]);
        float sum = 0.f;
#pragma unroll
        for (int kk = 0; kk < Kk; kk++) {
            float e = expf(w_s[kk][tid] - mx);
            w_s[kk][tid] = e;
            sum += e;
        }
        float rs = 1.0f / sum;
#pragma unroll
        for (int kk = 0; kk < Kk; kk++) w_s[kk][tid] *= rs;
    }
    __syncthreads();

    // weighted neighbor reduction
    float acc = 0.f;
    int dd = c & 31;
#pragma unroll
    for (int kk = 0; kk < Kk; kk++)
        acc = fmaf(vreg[kk], w_s[kk][dd], acc);
    out[((size_t)b * Cc + c) * Nn + n] = acc;
}

// ============================================================
// launch — 4 launches/call so ncu (-s 5) lands on fused_kernel
// ============================================================
extern "C" void kernel_launch(void* const* d_in, const int* in_sizes, int n_in,
                              void* d_out, int out_size)
{
    const float* xyz  = (const float*)d_in[0];
    const float* feat = (const float*)d_in[1];
    const float* Wq = (const float*)d_in[2];   const float* bqp = (const float*)d_in[3];
    const float* Wk = (const float*)d_in[4];   const float* bkp = (const float*)d_in[5];
    const float* Wv = (const float*)d_in[6];   const float* bvp = (const float*)d_in[7];
    const float* Wp1 = (const float*)d_in[8];  const float* bp1 = (const float*)d_in[9];
    const float* g1  = (const float*)d_in[10]; const float* b1  = (const float*)d_in[11];
    const float* Wp2 = (const float*)d_in[12]; const float* bp2 = (const float*)d_in[13];
    const float* g0  = (const float*)d_in[14]; const float* b0  = (const float*)d_in[15];
    const float* Ww1 = (const float*)d_in[16]; const float* bw1 = (const float*)d_in[17];
    const float* g2  = (const float*)d_in[18]; const float* b2  = (const float*)d_in[19];
    const float* Ww2 = (const float*)d_in[20]; const float* bw2 = (const float*)d_in[21];
    float* out = (float*)d_out;

    dim3 ggrid(Nn / GM_BM, Cc / GM_BN, 6);
    qkv_kernel<<<ggrid, 256>>>(feat, Wq, bqp, Wk, bkp, Wv, bvp);

    dim3 pgrid(Nn / KNN_TPB, NR, Bq);
    knn_part_kernel<<<pgrid, KNN_TPB>>>(xyz);

    dim3 mgrid(Nn / KNN_TPB, Bq);
    knn_merge_kernel<<<mgrid, KNN_TPB>>>();

    fused_kernel<<<Bq * Nn, 256>>>(xyz,
                                   Wp1, bp1, g1, b1, Wp2, bp2,
                                   g0, b0, Ww1, bw1, g2, b2, Ww2, bw2,
                                   out);
}

// round 10
// speedup vs baseline: 1.9130x; 1.4142x over previous
#include <cuda_runtime.h>
#include <math.h>

#define Bq 2
#define Nn 8192
#define Cc 256
#define Kk 16
#define Dd 32
#define NR 4            // KNN candidate ranges
#define RANGE (Nn / NR) // 2048
#define BN_INV 0.99999500003749969f

// ---- scratch (no cudaMalloc allowed) ----
__device__ float g_q[Bq * Nn * Cc];   // [b][n][c] point-major
__device__ float g_k[Bq * Nn * Cc];
__device__ float g_v[Bq * Nn * Cc];
__device__ int   g_idx[Bq * Nn * Kk];
__device__ float g_pd[Bq * Nn * NR * Kk];   // partial top-16 d2
__device__ int   g_pi[Bq * Nn * NR * Kk];   // partial top-16 idx

// ============================================================
// exact fp32 helpers
// ============================================================
__device__ __forceinline__ float2 two_sum(float a, float b) {
    float s  = __fadd_rn(a, b);
    float bp = __fsub_rn(s, a);
    float e  = __fadd_rn(__fsub_rn(a, __fsub_rn(s, bp)), __fsub_rn(b, bp));
    return make_float2(s, e);
}
__device__ __forceinline__ float2 two_prod(float a, float b) {
    float p = __fmul_rn(a, b);
    float e = __fmaf_rn(a, b, -p);
    return make_float2(p, e);
}

// ============================================================
// Kernel 1: QKV 1x1 conv as tiled SGEMM — one matrix per launch
// ============================================================
#define GM_BM 128
#define GM_BN 64
#define GM_BK 16

__global__ __launch_bounds__(256) void qkv_kernel(
    const float* __restrict__ feat,
    const float* __restrict__ W, const float* __restrict__ bias,
    float* __restrict__ outbase)
{
    int b = blockIdx.z;
    int n0 = blockIdx.x * GM_BM;
    int o0 = blockIdx.y * GM_BN;

    __shared__ __align__(16) float As[GM_BK][GM_BM];
    __shared__ float Bs[GM_BK][GM_BN + 1];

    const float* fb = feat + (size_t)b * Cc * Nn;
    int tid = threadIdx.x;
    int ty = tid >> 4;
    int tx = tid & 15;

    float acc[8][4];
#pragma unroll
    for (int i = 0; i < 8; i++)
#pragma unroll
        for (int j = 0; j < 4; j++) acc[i][j] = 0.f;

    for (int c0 = 0; c0 < Cc; c0 += GM_BK) {
        {
            int r = tid >> 4;
            int col = (tid & 15) * 8;
            const float* src = fb + (size_t)(c0 + r) * Nn + n0 + col;
            float4 v0 = *(const float4*)(src);
            float4 v1 = *(const float4*)(src + 4);
            *(float4*)&As[r][col]     = v0;
            *(float4*)&As[r][col + 4] = v1;
        }
        {
            int oo  = tid >> 2;
            int kc4 = (tid & 3) * 4;
            const float* src = W + (size_t)(o0 + oo) * Cc + c0 + kc4;
            float4 v = *(const float4*)src;
            Bs[kc4 + 0][oo] = v.x;
            Bs[kc4 + 1][oo] = v.y;
            Bs[kc4 + 2][oo] = v.z;
            Bs[kc4 + 3][oo] = v.w;
        }
        __syncthreads();
#pragma unroll
        for (int kc = 0; kc < GM_BK; kc++) {
            float a[8], bb[4];
#pragma unroll
            for (int i = 0; i < 8; i++) a[i] = As[kc][ty * 8 + i];
#pragma unroll
            for (int j = 0; j < 4; j++) bb[j] = Bs[kc][tx * 4 + j];
#pragma unroll
            for (int i = 0; i < 8; i++)
#pragma unroll
                for (int j = 0; j < 4; j++)
                    acc[i][j] = fmaf(a[i], bb[j], acc[i][j]);
        }
        __syncthreads();
    }

    float* ob = outbase + (size_t)b * Nn * Cc;
    float4 bv4 = *(const float4*)(bias + o0 + tx * 4);
#pragma unroll
    for (int i = 0; i < 8; i++) {
        int n = n0 + ty * 8 + i;
        float4 r;
        r.x = fmaxf(acc[i][0] + bv4.x, 0.f);
        r.y = fmaxf(acc[i][1] + bv4.y, 0.f);
        r.z = fmaxf(acc[i][2] + bv4.z, 0.f);
        r.w = fmaxf(acc[i][3] + bv4.w, 0.f);
        *(float4*)&ob[(size_t)n * Cc + o0 + tx * 4] = r;
    }
}

// ============================================================
// Kernel 2a: KNN partial — deferred-drain scan.
// Main loop is branch-free (filter + predicated u8 append).
// Drain recomputes the FROZEN exact d2 and does the identical
// strict-< ascending insertion => identical set and order.
// Stale chunk-start threshold is only looser => no misses.
// ============================================================
#define KNN_TPB 128
#define KNN_TILE 256
#define CHUNK 64

__global__ __launch_bounds__(KNN_TPB) void knn_part_kernel(const float* __restrict__ xyz)
{
    int b = blockIdx.z;
    int r = blockIdx.y;
    int n = blockIdx.x * KNN_TPB + threadIdx.x;
    int tid = threadIdx.x;
    const float* xb = xyz + (size_t)b * Nn * 3;

    float qx = xb[n * 3 + 0], qy = xb[n * 3 + 1], qz = xb[n * 3 + 2];

    float sqn_hi, sqn_lo;
    {
        float2 q0 = two_prod(qx, qx), q1 = two_prod(qy, qy), q2 = two_prod(qz, qz);
        float2 s01 = two_sum(q0.x, q1.x);
        float2 s   = two_sum(s01.x, q2.x);
        sqn_hi = s.x;
        sqn_lo = s01.y + s.y + q0.y + q1.y + q2.y;
    }

    float bd[Kk];
    int   bi[Kk];
#pragma unroll
    for (int i = 0; i < Kk; i++) { bd[i] = 3.4e38f; bi[i] = 0; }
    float cmax = 3.4e38f;

    __shared__ float4 tile[KNN_TILE];
    __shared__ float  tlo[KNN_TILE];
    __shared__ unsigned char buf[CHUNK][KNN_TPB];   // 8KB

    int mbase = r * RANGE;
    for (int m0 = mbase; m0 < mbase + RANGE; m0 += KNN_TILE) {
        __syncthreads();
        for (int j = tid; j < KNN_TILE; j += KNN_TPB) {
            float x = xb[(m0 + j) * 3 + 0];
            float y = xb[(m0 + j) * 3 + 1];
            float z = xb[(m0 + j) * 3 + 2];
            float2 p0 = two_prod(x, x), p1 = two_prod(y, y), p2 = two_prod(z, z);
            float2 s01 = two_sum(p0.x, p1.x);
            float2 s   = two_sum(s01.x, p2.x);
            tile[j] = make_float4(x, y, z, s.x);
            tlo[j]  = s01.y + s.y + p0.y + p1.y + p2.y;
        }
        __syncthreads();

        for (int cb = 0; cb < KNN_TILE; cb += CHUNK) {
            float thr = cmax + 1e-5f;     // stale => only looser => safe
            int cnt = 0;
            // branch-free filter pass
#pragma unroll 4
            for (int j64 = 0; j64 < CHUNK; j64++) {
                float4 cpt = tile[cb + j64];
                float dot = __fmaf_rn(qz, cpt.z,
                            __fmaf_rn(qy, cpt.y,
                            __fmul_rn(qx, cpt.x)));
                float m2dot = __fadd_rn(dot, dot);
                float cheap = __fsub_rn(__fadd_rn(sqn_hi, cpt.w), m2dot);
                bool hit = cheap < thr;
                buf[cnt][tid] = (unsigned char)j64;   // unconditional; garbage overwritten
                cnt += hit;
            }
            // drain (ascending j => scan order preserved)
            for (int t = 0; t < cnt; t++) {
                int j = cb + (int)buf[t][tid];
                float4 cpt = tile[j];
                float dot = __fmaf_rn(qz, cpt.z,
                            __fmaf_rn(qy, cpt.y,
                            __fmul_rn(qx, cpt.x)));
                float m2dot = __fadd_rn(dot, dot);
                float2 u1 = two_sum(sqn_hi, cpt.w);
                float2 u2 = two_sum(u1.x, -m2dot);
                float d2 = u2.x + (((u1.y + u2.y) + sqn_lo) + tlo[j]);
                if (d2 < bd[Kk - 1]) {
                    float v = d2;
                    int ii = m0 + j;
#pragma unroll
                    for (int i = 0; i < Kk; i++) {
                        if (v < bd[i]) {
                            float tv = bd[i]; int ti = bi[i];
                            bd[i] = v; bi[i] = ii;
                            v = tv; ii = ti;
                        }
                    }
                }
            }
            cmax = bd[Kk - 1];
        }
    }

    size_t o = (((size_t)(b * Nn) + n) * NR + r) * Kk;
#pragma unroll
    for (int i = 0; i < Kk; i++) { g_pd[o + i] = bd[i]; g_pi[o + i] = bi[i]; }
}

// ============================================================
// Kernel 2b: KNN merge (unchanged)
// ============================================================
__global__ __launch_bounds__(KNN_TPB) void knn_merge_kernel()
{
    int b = blockIdx.y;
    int n = blockIdx.x * KNN_TPB + threadIdx.x;

    float bd[Kk];
    int   bi[Kk];
#pragma unroll
    for (int i = 0; i < Kk; i++) { bd[i] = 3.4e38f; bi[i] = 0; }

    size_t base = ((size_t)(b * Nn) + n) * NR * Kk;
    for (int e = 0; e < NR * Kk; e++) {
        float v = g_pd[base + e];
        int  ii = g_pi[base + e];
        if (v < bd[Kk - 1]) {
#pragma unroll
            for (int i = 0; i < Kk; i++) {
                if (v < bd[i]) {
                    float tv = bd[i]; int ti = bi[i];
                    bd[i] = v; bi[i] = ii;
                    v = tv; ii = ti;
                }
            }
        }
    }

    int* op = g_idx + ((size_t)(b * Nn) + n) * Kk;
#pragma unroll
    for (int i = 0; i < Kk; i++) op[i] = bi[i];
}

// ============================================================
// Kernel 3: fused per-point attention
// phase 3 reblocked: R=4 d-outputs per wv load => LDS /4
// ============================================================
__global__ __launch_bounds__(256, 2) void fused_kernel(
    const float* __restrict__ xyz,
    const float* __restrict__ Wp1, const float* __restrict__ bp1,
    const float* __restrict__ g1,  const float* __restrict__ b1,
    const float* __restrict__ Wp2, const float* __restrict__ bp2,
    const float* __restrict__ g0,  const float* __restrict__ b0,
    const float* __restrict__ Ww1, const float* __restrict__ bw1,
    const float* __restrict__ g2,  const float* __restrict__ b2,
    const float* __restrict__ Ww2, const float* __restrict__ bw2,
    float* __restrict__ out)
{
    int bx = blockIdx.x;
    int b = bx >> 13;
    int n = bx & (Nn - 1);
    int tid = threadIdx.x;
    int c = tid;
    int warp = tid >> 5;
    int lane = tid & 31;

    __shared__ __align__(16) float wv_s[Kk][Cc];
    __shared__ float w1_all[Kk][Dd];
    __shared__ float w_s[Kk][Dd];
    __shared__ float w2t_s[Dd * Dd];
    __shared__ float ts_s[Kk][3];
    __shared__ int   idx_s[Kk];

    for (int i = tid; i < Dd * Dd; i += 256)
        w2t_s[i] = Ww2[(i & 31) * Dd + (i >> 5)];
    if (tid < Kk) idx_s[tid] = g_idx[((size_t)(b * Nn) + n) * Kk + tid];

    float xqc  = g_q[((size_t)(b * Nn) + n) * Cc + c];
    float wp20 = Wp2[c * 3 + 0], wp21 = Wp2[c * 3 + 1], wp22 = Wp2[c * 3 + 2];
    float bp2c = bp2[c];
    float s0c = g0[c] * BN_INV, h0c = b0[c];
    float bw2r = bw2[tid & 31];

    // phase-3 weights: warp handles d = 4*warp..4*warp+3;
    // lane covers c in {4*lane..4*lane+3, 128+4*lane..128+4*lane+3}
    float w4[4][8];
#pragma unroll
    for (int i = 0; i < 4; i++) {
        const float* wr = Ww1 + (size_t)(4 * warp + i) * Cc + 4 * lane;
        float4 t0 = *(const float4*)(wr);
        float4 t1 = *(const float4*)(wr + 128);
        w4[i][0] = t0.x; w4[i][1] = t0.y; w4[i][2] = t0.z; w4[i][3] = t0.w;
        w4[i][4] = t1.x; w4[i][5] = t1.y; w4[i][6] = t1.z; w4[i][7] = t1.w;
    }
    int d_l = 4 * warp + (lane & 3);
    float bw1_l = bw1[d_l];
    float s2_l  = g2[d_l] * BN_INV;
    float h2_l  = b2[d_l];

    __syncthreads();

    // phase 1: ts for all 16 neighbors (48 threads)
    if (tid < Kk * 3) {
        int k = tid / 3, o = tid % 3;
        int m = idx_s[k];
        const float* p = xyz + ((size_t)(b * Nn) + m) * 3;
        float p0 = p[0], p1 = p[1], p2 = p[2];
        float u = Wp1[o * 3 + 0] * p0 + Wp1[o * 3 + 1] * p1
                + Wp1[o * 3 + 2] * p2 + bp1[o];
        u = u * (g1[o] * BN_INV) + b1[o];
        ts_s[k][o] = fmaxf(u, 0.f);
    }
    __syncthreads();

    // phase 2: pr / wv / v (frozen arithmetic)
    float vreg[Kk];
#pragma unroll 4
    for (int kk = 0; kk < Kk; kk++) {
        int m = idx_s[kk];
        float t0 = ts_s[kk][0], t1 = ts_s[kk][1], t2 = ts_s[kk][2];
        float pr = fmaxf(wp20 * t0 + wp21 * t1 + wp22 * t2 + bp2c, 0.f);
        size_t base = ((size_t)(b * Nn) + m) * Cc + c;
        float xk = g_k[base];
        float xv = g_v[base];
        wv_s[kk][c] = fmaxf((xk - xqc + pr) * s0c + h0c, 0.f);
        vreg[kk] = xv + pr;
    }
    __syncthreads();

    // phase 3: w1 GEMV, R=4 d per thread, 32-lane butterfly
#pragma unroll 4
    for (int kk = 0; kk < Kk; kk++) {
        const float4* wrow = (const float4*)(&wv_s[kk][0]);
        float4 v0 = wrow[lane];
        float4 v1 = wrow[lane + 32];
        float a0 = 0.f, a1 = 0.f, a2 = 0.f, a3 = 0.f;
        a0 = fmaf(w4[0][0], v0.x, a0); a0 = fmaf(w4[0][1], v0.y, a0);
        a0 = fmaf(w4[0][2], v0.z, a0); a0 = fmaf(w4[0][3], v0.w, a0);
        a0 = fmaf(w4[0][4], v1.x, a0); a0 = fmaf(w4[0][5], v1.y, a0);
        a0 = fmaf(w4[0][6], v1.z, a0); a0 = fmaf(w4[0][7], v1.w, a0);
        a1 = fmaf(w4[1][0], v0.x, a1); a1 = fmaf(w4[1][1], v0.y, a1);
        a1 = fmaf(w4[1][2], v0.z, a1); a1 = fmaf(w4[1][3], v0.w, a1);
        a1 = fmaf(w4[1][4], v1.x, a1); a1 = fmaf(w4[1][5], v1.y, a1);
        a1 = fmaf(w4[1][6], v1.z, a1); a1 = fmaf(w4[1][7], v1.w, a1);
        a2 = fmaf(w4[2][0], v0.x, a2); a2 = fmaf(w4[2][1], v0.y, a2);
        a2 = fmaf(w4[2][2], v0.z, a2); a2 = fmaf(w4[2][3], v0.w, a2);
        a2 = fmaf(w4[2][4], v1.x, a2); a2 = fmaf(w4[2][5], v1.y, a2);
        a2 = fmaf(w4[2][6], v1.z, a2); a2 = fmaf(w4[2][7], v1.w, a2);
        a3 = fmaf(w4[3][0], v0.x, a3); a3 = fmaf(w4[3][1], v0.y, a3);
        a3 = fmaf(w4[3][2], v0.z, a3); a3 = fmaf(w4[3][3], v0.w, a3);
        a3 = fmaf(w4[3][4], v1.x, a3); a3 = fmaf(w4[3][5], v1.y, a3);
        a3 = fmaf(w4[3][6], v1.z, a3); a3 = fmaf(w4[3][7], v1.w, a3);
#pragma unroll
        for (int off = 16; off > 0; off >>= 1) {
            a0 += __shfl_xor_sync(0xffffffffu, a0, off);
            a1 += __shfl_xor_sync(0xffffffffu, a1, off);
            a2 += __shfl_xor_sync(0xffffffffu, a2, off);
            a3 += __shfl_xor_sync(0xffffffffu, a3, off);
        }
        if (lane < 4) {
            float t01 = (lane & 1) ? a1 : a0;
            float t23 = (lane & 1) ? a3 : a2;
            float part = (lane & 2) ? t23 : t01;
            float u = (part + bw1_l) * s2_l + h2_l;
            w1_all[kk][4 * warp + lane] = fmaxf(u, 0.f);
        }
    }
    __syncthreads();

    // phase 4: w2 — 512 outputs, 2 per thread
#pragma unroll
    for (int r2 = 0; r2 < 2; r2++) {
        int oidx = tid + r2 * 256;
        int k = oidx >> 5, e = oidx & 31;
        float acc = bw2r;
#pragma unroll
        for (int dd = 0; dd < Dd; dd++)
            acc = fmaf(w2t_s[dd * Dd + e], w1_all[k][dd], acc);
        w_s[k][e] = fmaxf(acc, 0.f);
    }
    __syncthreads();

    // softmax over K per channel e
    if (tid < Dd) {
        float mx = -3.4e38f;
#pragma unroll
        for (int kk = 0; kk < Kk; kk++) mx = fmaxf(mx, w_s[kk][tid]);
        float sum = 0.f;
#pragma unroll
        for (int kk = 0; kk < Kk; kk++) {
            float e = expf(w_s[kk][tid] - mx);
            w_s[kk][tid] = e;
            sum += e;
        }
        float rs = 1.0f / sum;
#pragma unroll
        for (int kk = 0; kk < Kk; kk++) w_s[kk][tid] *= rs;
    }
    __syncthreads();

    // weighted neighbor reduction
    float acc = 0.f;
    int dd = c & 31;
#pragma unroll
    for (int kk = 0; kk < Kk; kk++)
        acc = fmaf(vreg[kk], w_s[kk][dd], acc);
    out[((size_t)b * Cc + c) * Nn + n] = acc;
}

// ============================================================
// launch — 3 qkv launches put knn_part at ncu index 5
// ============================================================
extern "C" void kernel_launch(void* const* d_in, const int* in_sizes, int n_in,
                              void* d_out, int out_size)
{
    const float* xyz  = (const float*)d_in[0];
    const float* feat = (const float*)d_in[1];
    const float* Wq = (const float*)d_in[2];   const float* bqp = (const float*)d_in[3];
    const float* Wk = (const float*)d_in[4];   const float* bkp = (const float*)d_in[5];
    const float* Wv = (const float*)d_in[6];   const float* bvp = (const float*)d_in[7];
    const float* Wp1 = (const float*)d_in[8];  const float* bp1 = (const float*)d_in[9];
    const float* g1  = (const float*)d_in[10]; const float* b1  = (const float*)d_in[11];
    const float* Wp2 = (const float*)d_in[12]; const float* bp2 = (const float*)d_in[13];
    const float* g0  = (const float*)d_in[14]; const float* b0  = (const float*)d_in[15];
    const float* Ww1 = (const float*)d_in[16]; const float* bw1 = (const float*)d_in[17];
    const float* g2  = (const float*)d_in[18]; const float* b2  = (const float*)d_in[19];
    const float* Ww2 = (const float*)d_in[20]; const float* bw2 = (const float*)d_in[21];
    float* out = (float*)d_out;

    float* gq; cudaGetSymbolAddress((void**)&gq, g_q);
    float* gk; cudaGetSymbolAddress((void**)&gk, g_k);
    float* gv; cudaGetSymbolAddress((void**)&gv, g_v);

    dim3 ggrid(Nn / GM_BM, Cc / GM_BN, Bq);
    qkv_kernel<<<ggrid, 256>>>(feat, Wq, bqp, gq);
    qkv_kernel<<<ggrid, 256>>>(feat, Wk, bkp, gk);
    qkv_kernel<<<ggrid, 256>>>(feat, Wv, bvp, gv);

    dim3 pgrid(Nn / KNN_TPB, NR, Bq);
    knn_part_kernel<<<pgrid, KNN_TPB>>>(xyz);

    dim3 mgrid(Nn / KNN_TPB, Bq);
    knn_merge_kernel<<<mgrid, KNN_TPB>>>();

    fused_kernel<<<Bq * Nn, 256>>>(xyz,
                                   Wp1, bp1, g1, b1, Wp2, bp2,
                                   g0, b0, Ww1, bw1, g2, b2, Ww2, bw2,
                                   out);
}

// round 11
// speedup vs baseline: 1.9189x; 1.0031x over previous
#include <cuda_runtime.h>
#include <math.h>

#define Bq 2
#define Nn 8192
#define Cc 256
#define Kk 16
#define Dd 32
#define NR 4
#define RANGE (Nn / NR)
#define BN_INV 0.99999500003749969f

// ---- scratch ----
__device__ float g_q[Bq * Nn * Cc];
__device__ float g_k[Bq * Nn * Cc];
__device__ float g_v[Bq * Nn * Cc];
__device__ float g_pr[Bq * Nn * Cc];
__device__ float g_vp[Bq * Nn * Cc];
__device__ int   g_idx[Bq * Nn * Kk];
__device__ float g_pd[Bq * Nn * NR * Kk];
__device__ int   g_pi[Bq * Nn * NR * Kk];

__device__ __forceinline__ float2 two_sum(float a, float b) {
    float s  = __fadd_rn(a, b);
    float bp = __fsub_rn(s, a);
    float e  = __fadd_rn(__fsub_rn(a, __fsub_rn(s, bp)), __fsub_rn(b, bp));
    return make_float2(s, e);
}
__device__ __forceinline__ float2 two_prod(float a, float b) {
    float p = __fmul_rn(a, b);
    float e = __fmaf_rn(a, b, -p);
    return make_float2(p, e);
}

// ============================================================
// SUPER kernel: knn_part blocks first, then qkv blocks
// ============================================================
#define GM_BM 128
#define GM_BN 64
#define GM_BK 16
#define KNN_Q 256
#define KNN_TILE 256
#define CHUNK 64
#define KNN_NBLK ((Nn / KNN_Q) * NR * Bq)          // 256
#define QKV_NBLK ((Nn / GM_BM) * (Cc / GM_BN) * Bq) // 512 per matrix

__global__ __launch_bounds__(256, 3) void super_kernel(
    const float* __restrict__ feat, const float* __restrict__ xyz,
    const float* __restrict__ Wq, const float* __restrict__ bq,
    const float* __restrict__ Wk, const float* __restrict__ bk,
    const float* __restrict__ Wv, const float* __restrict__ bv)
{
    __shared__ __align__(16) union SM {
        struct { float As[GM_BK][GM_BM]; float Bs[GM_BK][GM_BN + 1]; } g;
        struct { float4 tile[KNN_TILE]; float tlo[KNN_TILE];
                 unsigned char buf[CHUNK][264]; } k;
    } sm;

    int bid = blockIdx.x;
    int tid = threadIdx.x;

    if (bid < KNN_NBLK) {
        // ---------------- KNN role ----------------
        int b   = bid / ((Nn / KNN_Q) * NR);
        int rem = bid % ((Nn / KNN_Q) * NR);
        int r   = rem >> 5;                 // Nn/KNN_Q == 32
        int qb  = rem & 31;
        int n   = qb * KNN_Q + tid;
        const float* xb = xyz + (size_t)b * Nn * 3;

        float qx = xb[n * 3 + 0], qy = xb[n * 3 + 1], qz = xb[n * 3 + 2];

        float sqn_hi, sqn_lo;
        {
            float2 q0 = two_prod(qx, qx), q1 = two_prod(qy, qy), q2 = two_prod(qz, qz);
            float2 s01 = two_sum(q0.x, q1.x);
            float2 s   = two_sum(s01.x, q2.x);
            sqn_hi = s.x;
            sqn_lo = s01.y + s.y + q0.y + q1.y + q2.y;
        }
        float qx2 = -2.0f * qx, qy2 = -2.0f * qy, qz2 = -2.0f * qz;

        float bd[Kk];
        int   bi[Kk];
#pragma unroll
        for (int i = 0; i < Kk; i++) { bd[i] = 3.4e38f; bi[i] = 0; }
        float cmax = 3.4e38f;

        int mbase = r * RANGE;
        for (int m0 = mbase; m0 < mbase + RANGE; m0 += KNN_TILE) {
            __syncthreads();
            {
                int j = tid;   // KNN_TILE == blockDim
                float x = xb[(m0 + j) * 3 + 0];
                float y = xb[(m0 + j) * 3 + 1];
                float z = xb[(m0 + j) * 3 + 2];
                float2 p0 = two_prod(x, x), p1 = two_prod(y, y), p2 = two_prod(z, z);
                float2 s01 = two_sum(p0.x, p1.x);
                float2 s   = two_sum(s01.x, p2.x);
                sm.k.tile[j] = make_float4(x, y, z, s.x);
                sm.k.tlo[j]  = s01.y + s.y + p0.y + p1.y + p2.y;
            }
            __syncthreads();

            for (int cb = 0; cb < KNN_TILE; cb += CHUNK) {
                // loose fp32 threshold (conservative: margin 2e-5 >> 1.5e-6 err)
                float thrp = (cmax + 2e-5f) - sqn_hi;
                int cnt = 0;
#pragma unroll 4
                for (int j64 = 0; j64 < CHUNK; j64++) {
                    float4 cpt = sm.k.tile[cb + j64];
                    float t = fmaf(qx2, cpt.x, fmaf(qy2, cpt.y,
                              fmaf(qz2, cpt.z, cpt.w)));
                    bool hit = t < thrp;
                    sm.k.buf[cnt][tid] = (unsigned char)j64;
                    cnt += hit;
                }
                for (int t = 0; t < cnt; t++) {
                    int j = cb + (int)sm.k.buf[t][tid];
                    float4 cpt = sm.k.tile[j];
                    // FROZEN exact path (identical to R7-passing kernel)
                    float dot = __fmaf_rn(qz, cpt.z,
                                __fmaf_rn(qy, cpt.y,
                                __fmul_rn(qx, cpt.x)));
                    float m2dot = __fadd_rn(dot, dot);
                    float2 u1 = two_sum(sqn_hi, cpt.w);
                    float2 u2 = two_sum(u1.x, -m2dot);
                    float d2 = u2.x + (((u1.y + u2.y) + sqn_lo) + sm.k.tlo[j]);
                    if (d2 < bd[Kk - 1]) {
                        float v = d2;
                        int ii = m0 + j;
#pragma unroll
                        for (int i = 0; i < Kk; i++) {
                            if (v < bd[i]) {
                                float tv = bd[i]; int ti = bi[i];
                                bd[i] = v; bi[i] = ii;
                                v = tv; ii = ti;
                            }
                        }
                    }
                }
                cmax = bd[Kk - 1];
            }
        }

        size_t o = (((size_t)(b * Nn) + n) * NR + r) * Kk;
#pragma unroll
        for (int i = 0; i < Kk; i++) { g_pd[o + i] = bd[i]; g_pi[o + i] = bi[i]; }

    } else {
        // ---------------- QKV GEMM role ----------------
        int q   = bid - KNN_NBLK;
        int mat = q / QKV_NBLK;
        int rem = q % QKV_NBLK;
        int b   = rem >> 8;          // 256 blocks per (mat,b)
        int t2  = rem & 255;
        int n0  = (t2 & 63) * GM_BM;
        int o0  = (t2 >> 6) * GM_BN;

        const float* W    = (mat == 0) ? Wq : (mat == 1) ? Wk : Wv;
        const float* bias = (mat == 0) ? bq : (mat == 1) ? bk : bv;
        float* out        = (mat == 0) ? g_q : (mat == 1) ? g_k : g_v;

        const float* fb = feat + (size_t)b * Cc * Nn;
        int ty = tid >> 4;
        int tx = tid & 15;

        float acc[8][4];
#pragma unroll
        for (int i = 0; i < 8; i++)
#pragma unroll
            for (int j = 0; j < 4; j++) acc[i][j] = 0.f;

        for (int c0 = 0; c0 < Cc; c0 += GM_BK) {
            {
                int r2 = tid >> 4;
                int col = (tid & 15) * 8;
                const float* src = fb + (size_t)(c0 + r2) * Nn + n0 + col;
                float4 v0 = *(const float4*)(src);
                float4 v1 = *(const float4*)(src + 4);
                *(float4*)&sm.g.As[r2][col]     = v0;
                *(float4*)&sm.g.As[r2][col + 4] = v1;
            }
            {
                int oo  = tid >> 2;
                int kc4 = (tid & 3) * 4;
                const float* src = W + (size_t)(o0 + oo) * Cc + c0 + kc4;
                float4 v = *(const float4*)src;
                sm.g.Bs[kc4 + 0][oo] = v.x;
                sm.g.Bs[kc4 + 1][oo] = v.y;
                sm.g.Bs[kc4 + 2][oo] = v.z;
                sm.g.Bs[kc4 + 3][oo] = v.w;
            }
            __syncthreads();
#pragma unroll
            for (int kc = 0; kc < GM_BK; kc++) {
                float a[8], bb[4];
#pragma unroll
                for (int i = 0; i < 8; i++) a[i] = sm.g.As[kc][ty * 8 + i];
#pragma unroll
                for (int j = 0; j < 4; j++) bb[j] = sm.g.Bs[kc][tx * 4 + j];
#pragma unroll
                for (int i = 0; i < 8; i++)
#pragma unroll
                    for (int j = 0; j < 4; j++)
                        acc[i][j] = fmaf(a[i], bb[j], acc[i][j]);
            }
            __syncthreads();
        }

        float* ob = out + (size_t)b * Nn * Cc;
        float4 bv4 = *(const float4*)(bias + o0 + tx * 4);
#pragma unroll
        for (int i = 0; i < 8; i++) {
            int n = n0 + ty * 8 + i;
            float4 r2;
            r2.x = fmaxf(acc[i][0] + bv4.x, 0.f);
            r2.y = fmaxf(acc[i][1] + bv4.y, 0.f);
            r2.z = fmaxf(acc[i][2] + bv4.z, 0.f);
            r2.w = fmaxf(acc[i][3] + bv4.w, 0.f);
            *(float4*)&ob[(size_t)n * Cc + o0 + tx * 4] = r2;
        }
    }
}

// ============================================================
// KNN merge (unchanged)
// ============================================================
#define KNN_TPB 128

__global__ __launch_bounds__(KNN_TPB) void knn_merge_kernel()
{
    int b = blockIdx.y;
    int n = blockIdx.x * KNN_TPB + threadIdx.x;

    float bd[Kk];
    int   bi[Kk];
#pragma unroll
    for (int i = 0; i < Kk; i++) { bd[i] = 3.4e38f; bi[i] = 0; }

    size_t base = ((size_t)(b * Nn) + n) * NR * Kk;
    for (int e = 0; e < NR * Kk; e++) {
        float v = g_pd[base + e];
        int  ii = g_pi[base + e];
        if (v < bd[Kk - 1]) {
#pragma unroll
            for (int i = 0; i < Kk; i++) {
                if (v < bd[i]) {
                    float tv = bd[i]; int ti = bi[i];
                    bd[i] = v; bi[i] = ii;
                    v = tv; ii = ti;
                }
            }
        }
    }

    int* op = g_idx + ((size_t)(b * Nn) + n) * Kk;
#pragma unroll
    for (int i = 0; i < Kk; i++) op[i] = bi[i];
}

// ============================================================
// prep: per (b,m,c) query-independent work — pr and v = xv + pr
// (expressions copied verbatim from the passing fused kernel)
// ============================================================
__global__ __launch_bounds__(256) void prep_kernel(
    const float* __restrict__ xyz,
    const float* __restrict__ Wp1, const float* __restrict__ bp1,
    const float* __restrict__ g1,  const float* __restrict__ b1,
    const float* __restrict__ Wp2, const float* __restrict__ bp2)
{
    int bm = blockIdx.x;            // b*Nn + m
    int c = threadIdx.x;
    const float* p = xyz + (size_t)bm * 3;
    float p0 = p[0], p1v = p[1], p2 = p[2];
    float t[3];
#pragma unroll
    for (int o = 0; o < 3; o++) {
        float u = Wp1[o * 3 + 0] * p0 + Wp1[o * 3 + 1] * p1v
                + Wp1[o * 3 + 2] * p2 + bp1[o];
        u = u * (g1[o] * BN_INV) + b1[o];
        t[o] = fmaxf(u, 0.f);
    }
    float wp20 = Wp2[c * 3 + 0], wp21 = Wp2[c * 3 + 1], wp22 = Wp2[c * 3 + 2];
    float pr = fmaxf(wp20 * t[0] + wp21 * t[1] + wp22 * t[2] + bp2[c], 0.f);
    size_t base = (size_t)bm * Cc + c;
    g_pr[base] = pr;
    float xv = g_v[base];
    g_vp[base] = xv + pr;
}

// ============================================================
// fused attention (phase 1 removed; 3 gathers; occ=3)
// ============================================================
__global__ __launch_bounds__(256, 3) void fused_kernel(
    const float* __restrict__ g0,  const float* __restrict__ b0,
    const float* __restrict__ Ww1, const float* __restrict__ bw1,
    const float* __restrict__ g2,  const float* __restrict__ b2,
    const float* __restrict__ Ww2, const float* __restrict__ bw2,
    float* __restrict__ out)
{
    int bx = blockIdx.x;
    int b = bx >> 13;
    int n = bx & (Nn - 1);
    int tid = threadIdx.x;
    int c = tid;
    int warp = tid >> 5;
    int lane = tid & 31;

    __shared__ __align__(16) float wv_s[Kk][Cc];
    __shared__ float w1_all[Kk][Dd];
    __shared__ float w_s[Kk][Dd];
    __shared__ float w2t_s[Dd * Dd];
    __shared__ int   idx_s[Kk];

    for (int i = tid; i < Dd * Dd; i += 256)
        w2t_s[i] = Ww2[(i & 31) * Dd + (i >> 5)];
    if (tid < Kk) idx_s[tid] = g_idx[((size_t)(b * Nn) + n) * Kk + tid];

    float xqc = g_q[((size_t)(b * Nn) + n) * Cc + c];
    float s0c = g0[c] * BN_INV, h0c = b0[c];
    float bw2r = bw2[tid & 31];

    float w4[4][8];
#pragma unroll
    for (int i = 0; i < 4; i++) {
        const float* wr = Ww1 + (size_t)(4 * warp + i) * Cc + 4 * lane;
        float4 t0 = *(const float4*)(wr);
        float4 t1 = *(const float4*)(wr + 128);
        w4[i][0] = t0.x; w4[i][1] = t0.y; w4[i][2] = t0.z; w4[i][3] = t0.w;
        w4[i][4] = t1.x; w4[i][5] = t1.y; w4[i][6] = t1.z; w4[i][7] = t1.w;
    }
    int d_l = 4 * warp + (lane & 3);
    float bw1_l = bw1[d_l];
    float s2_l  = g2[d_l] * BN_INV;
    float h2_l  = b2[d_l];

    __syncthreads();

    // phase 2: gather kp/pr/vp; frozen wv expression
    float vreg[Kk];
#pragma unroll 4
    for (int kk = 0; kk < Kk; kk++) {
        int m = idx_s[kk];
        size_t base = ((size_t)(b * Nn) + m) * Cc + c;
        float xk = g_k[base];
        float pr = g_pr[base];
        wv_s[kk][c] = fmaxf((xk - xqc + pr) * s0c + h0c, 0.f);
        vreg[kk] = g_vp[base];
    }
    __syncthreads();

    // phase 3: w1 GEMV, R=4 d per thread
#pragma unroll 4
    for (int kk = 0; kk < Kk; kk++) {
        const float4* wrow = (const float4*)(&wv_s[kk][0]);
        float4 v0 = wrow[lane];
        float4 v1 = wrow[lane + 32];
        float a0 = 0.f, a1 = 0.f, a2 = 0.f, a3 = 0.f;
        a0 = fmaf(w4[0][0], v0.x, a0); a0 = fmaf(w4[0][1], v0.y, a0);
        a0 = fmaf(w4[0][2], v0.z, a0); a0 = fmaf(w4[0][3], v0.w, a0);
        a0 = fmaf(w4[0][4], v1.x, a0); a0 = fmaf(w4[0][5], v1.y, a0);
        a0 = fmaf(w4[0][6], v1.z, a0); a0 = fmaf(w4[0][7], v1.w, a0);
        a1 = fmaf(w4[1][0], v0.x, a1); a1 = fmaf(w4[1][1], v0.y, a1);
        a1 = fmaf(w4[1][2], v0.z, a1); a1 = fmaf(w4[1][3], v0.w, a1);
        a1 = fmaf(w4[1][4], v1.x, a1); a1 = fmaf(w4[1][5], v1.y, a1);
        a1 = fmaf(w4[1][6], v1.z, a1); a1 = fmaf(w4[1][7], v1.w, a1);
        a2 = fmaf(w4[2][0], v0.x, a2); a2 = fmaf(w4[2][1], v0.y, a2);
        a2 = fmaf(w4[2][2], v0.z, a2); a2 = fmaf(w4[2][3], v0.w, a2);
        a2 = fmaf(w4[2][4], v1.x, a2); a2 = fmaf(w4[2][5], v1.y, a2);
        a2 = fmaf(w4[2][6], v1.z, a2); a2 = fmaf(w4[2][7], v1.w, a2);
        a3 = fmaf(w4[3][0], v0.x, a3); a3 = fmaf(w4[3][1], v0.y, a3);
        a3 = fmaf(w4[3][2], v0.z, a3); a3 = fmaf(w4[3][3], v0.w, a3);
        a3 = fmaf(w4[3][4], v1.x, a3); a3 = fmaf(w4[3][5], v1.y, a3);
        a3 = fmaf(w4[3][6], v1.z, a3); a3 = fmaf(w4[3][7], v1.w, a3);
#pragma unroll
        for (int off = 16; off > 0; off >>= 1) {
            a0 += __shfl_xor_sync(0xffffffffu, a0, off);
            a1 += __shfl_xor_sync(0xffffffffu, a1, off);
            a2 += __shfl_xor_sync(0xffffffffu, a2, off);
            a3 += __shfl_xor_sync(0xffffffffu, a3, off);
        }
        if (lane < 4) {
            float t01 = (lane & 1) ? a1 : a0;
            float t23 = (lane & 1) ? a3 : a2;
            float part = (lane & 2) ? t23 : t01;
            float u = (part + bw1_l) * s2_l + h2_l;
            w1_all[kk][4 * warp + lane] = fmaxf(u, 0.f);
        }
    }
    __syncthreads();

    // phase 4: w2
#pragma unroll
    for (int r2 = 0; r2 < 2; r2++) {
        int oidx = tid + r2 * 256;
        int k = oidx >> 5, e = oidx & 31;
        float acc = bw2r;
#pragma unroll
        for (int dd = 0; dd < Dd; dd++)
            acc = fmaf(w2t_s[dd * Dd + e], w1_all[k][dd], acc);
        w_s[k][e] = fmaxf(acc, 0.f);
    }
    __syncthreads();

    // softmax over K
    if (tid < Dd) {
        float mx = -3.4e38f;
#pragma unroll
        for (int kk = 0; kk < Kk; kk++) mx = fmaxf(mx, w_s[kk][tid]);
        float sum = 0.f;
#pragma unroll
        for (int kk = 0; kk < Kk; kk++) {
            float e = expf(w_s[kk][tid] - mx);
            w_s[kk][tid] = e;
            sum += e;
        }
        float rs = 1.0f / sum;
#pragma unroll
        for (int kk = 0; kk < Kk; kk++) w_s[kk][tid] *= rs;
    }
    __syncthreads();

    float acc = 0.f;
    int dd = c & 31;
#pragma unroll
    for (int kk = 0; kk < Kk; kk++)
        acc = fmaf(vreg[kk], w_s[kk][dd], acc);
    out[((size_t)b * Cc + c) * Nn + n] = acc;
}

// ============================================================
// launch: super, merge, prep, fused  (fused = ncu index 5)
// ============================================================
extern "C" void kernel_launch(void* const* d_in, const int* in_sizes, int n_in,
                              void* d_out, int out_size)
{
    const float* xyz  = (const float*)d_in[0];
    const float* feat = (const float*)d_in[1];
    const float* Wq = (const float*)d_in[2];   const float* bqp = (const float*)d_in[3];
    const float* Wk = (const float*)d_in[4];   const float* bkp = (const float*)d_in[5];
    const float* Wv = (const float*)d_in[6];   const float* bvp = (const float*)d_in[7];
    const float* Wp1 = (const float*)d_in[8];  const float* bp1 = (const float*)d_in[9];
    const float* g1  = (const float*)d_in[10]; const float* b1  = (const float*)d_in[11];
    const float* Wp2 = (const float*)d_in[12]; const float* bp2 = (const float*)d_in[13];
    const float* g0  = (const float*)d_in[14]; const float* b0  = (const float*)d_in[15];
    const float* Ww1 = (const float*)d_in[16]; const float* bw1 = (const float*)d_in[17];
    const float* g2  = (const float*)d_in[18]; const float* b2  = (const float*)d_in[19];
    const float* Ww2 = (const float*)d_in[20]; const float* bw2 = (const float*)d_in[21];
    float* out = (float*)d_out;

    super_kernel<<<KNN_NBLK + 3 * QKV_NBLK, 256>>>(feat, xyz,
                                                   Wq, bqp, Wk, bkp, Wv, bvp);

    dim3 mgrid(Nn / KNN_TPB, Bq);
    knn_merge_kernel<<<mgrid, KNN_TPB>>>();

    prep_kernel<<<Bq * Nn, 256>>>(xyz, Wp1, bp1, g1, b1, Wp2, bp2);

    fused_kernel<<<Bq * Nn, 256>>>(g0, b0, Ww1, bw1, g2, b2, Ww2, bw2, out);
}

// round 13
// speedup vs baseline: 1.9688x; 1.0260x over previous
#include <cuda_runtime.h>
#include <math.h>

#define Bq 2
#define Nn 8192
#define Cc 256
#define Kk 16
#define Dd 32
#define NR 4
#define RANGE (Nn / NR)
#define BN_INV 0.99999500003749969f

// ---- scratch ----
__device__ float  g_q[Bq * Nn * Cc];
__device__ float  g_k[Bq * Nn * Cc];
__device__ float  g_v[Bq * Nn * Cc];
__device__ float2 g_kv2[Bq * Nn * Cc];     // {xk+pr, xv+pr}
__device__ float  g_tmp[Bq * Nn * Cc];     // fused output, [b][n][c]
__device__ int    g_idx[Bq * Nn * Kk];
__device__ float  g_pd[Bq * Nn * NR * Kk];
__device__ int    g_pi[Bq * Nn * NR * Kk];

__device__ __forceinline__ float2 two_sum(float a, float b) {
    float s  = __fadd_rn(a, b);
    float bp = __fsub_rn(s, a);
    float e  = __fadd_rn(__fsub_rn(a, __fsub_rn(s, bp)), __fsub_rn(b, bp));
    return make_float2(s, e);
}
__device__ __forceinline__ float2 two_prod(float a, float b) {
    float p = __fmul_rn(a, b);
    float e = __fmaf_rn(a, b, -p);
    return make_float2(p, e);
}

// ============================================================
// SUPER kernel: knn_part blocks first, then qkv blocks
// ============================================================
#define GM_BM 128
#define GM_BN 64
#define GM_BK 16
#define KNN_Q 256
#define KNN_TILE 256
#define CHUNK 64
#define KNN_NBLK ((Nn / KNN_Q) * NR * Bq)
#define QKV_NBLK ((Nn / GM_BM) * (Cc / GM_BN) * Bq)

__global__ __launch_bounds__(256, 3) void super_kernel(
    const float* __restrict__ feat, const float* __restrict__ xyz,
    const float* __restrict__ Wq, const float* __restrict__ bq,
    const float* __restrict__ Wk, const float* __restrict__ bk,
    const float* __restrict__ Wv, const float* __restrict__ bv)
{
    __shared__ __align__(16) union SM {
        struct { float As[GM_BK][GM_BM]; float Bs[GM_BK][GM_BN + 1]; } g;
        struct { float4 tile[KNN_TILE]; float tlo[KNN_TILE];
                 unsigned char buf[CHUNK][264]; } k;
    } sm;

    int bid = blockIdx.x;
    int tid = threadIdx.x;

    if (bid < KNN_NBLK) {
        int b   = bid / ((Nn / KNN_Q) * NR);
        int rem = bid % ((Nn / KNN_Q) * NR);
        int r   = rem >> 5;
        int qb  = rem & 31;
        int n   = qb * KNN_Q + tid;
        const float* xb = xyz + (size_t)b * Nn * 3;

        float qx = xb[n * 3 + 0], qy = xb[n * 3 + 1], qz = xb[n * 3 + 2];

        float sqn_hi, sqn_lo;
        {
            float2 q0 = two_prod(qx, qx), q1 = two_prod(qy, qy), q2 = two_prod(qz, qz);
            float2 s01 = two_sum(q0.x, q1.x);
            float2 s   = two_sum(s01.x, q2.x);
            sqn_hi = s.x;
            sqn_lo = s01.y + s.y + q0.y + q1.y + q2.y;
        }
        float qx2 = -2.0f * qx, qy2 = -2.0f * qy, qz2 = -2.0f * qz;

        float bd[Kk];
        int   bi[Kk];
#pragma unroll
        for (int i = 0; i < Kk; i++) { bd[i] = 3.4e38f; bi[i] = 0; }
        float cmax = 3.4e38f;

        int mbase = r * RANGE;
        for (int m0 = mbase; m0 < mbase + RANGE; m0 += KNN_TILE) {
            __syncthreads();
            {
                int j = tid;
                float x = xb[(m0 + j) * 3 + 0];
                float y = xb[(m0 + j) * 3 + 1];
                float z = xb[(m0 + j) * 3 + 2];
                float2 p0 = two_prod(x, x), p1 = two_prod(y, y), p2 = two_prod(z, z);
                float2 s01 = two_sum(p0.x, p1.x);
                float2 s   = two_sum(s01.x, p2.x);
                sm.k.tile[j] = make_float4(x, y, z, s.x);
                sm.k.tlo[j]  = s01.y + s.y + p0.y + p1.y + p2.y;
            }
            __syncthreads();

            for (int cb = 0; cb < KNN_TILE; cb += CHUNK) {
                float thrp = (cmax + 2e-5f) - sqn_hi;
                int cnt = 0;
#pragma unroll 4
                for (int j64 = 0; j64 < CHUNK; j64++) {
                    float4 cpt = sm.k.tile[cb + j64];
                    float t = fmaf(qx2, cpt.x, fmaf(qy2, cpt.y,
                              fmaf(qz2, cpt.z, cpt.w)));
                    bool hit = t < thrp;
                    sm.k.buf[cnt][tid] = (unsigned char)j64;
                    cnt += hit;
                }
                for (int t = 0; t < cnt; t++) {
                    int j = cb + (int)sm.k.buf[t][tid];
                    float4 cpt = sm.k.tile[j];
                    // FROZEN exact path (identical to R7-passing kernel)
                    float dot = __fmaf_rn(qz, cpt.z,
                                __fmaf_rn(qy, cpt.y,
                                __fmul_rn(qx, cpt.x)));
                    float m2dot = __fadd_rn(dot, dot);
                    float2 u1 = two_sum(sqn_hi, cpt.w);
                    float2 u2 = two_sum(u1.x, -m2dot);
                    float d2 = u2.x + (((u1.y + u2.y) + sqn_lo) + sm.k.tlo[j]);
                    if (d2 < bd[Kk - 1]) {
                        float v = d2;
                        int ii = m0 + j;
#pragma unroll
                        for (int i = 0; i < Kk; i++) {
                            if (v < bd[i]) {
                                float tv = bd[i]; int ti = bi[i];
                                bd[i] = v; bi[i] = ii;
                                v = tv; ii = ti;
                            }
                        }
                    }
                }
                cmax = bd[Kk - 1];
            }
        }

        size_t o = (((size_t)(b * Nn) + n) * NR + r) * Kk;
#pragma unroll
        for (int i = 0; i < Kk; i++) { g_pd[o + i] = bd[i]; g_pi[o + i] = bi[i]; }

    } else {
        int q   = bid - KNN_NBLK;
        int mat = q / QKV_NBLK;
        int rem = q % QKV_NBLK;
        int b   = rem >> 8;
        int t2  = rem & 255;
        int n0  = (t2 & 63) * GM_BM;
        int o0  = (t2 >> 6) * GM_BN;

        const float* W    = (mat == 0) ? Wq : (mat == 1) ? Wk : Wv;
        const float* bias = (mat == 0) ? bq : (mat == 1) ? bk : bv;
        float* out        = (mat == 0) ? g_q : (mat == 1) ? g_k : g_v;

        const float* fb = feat + (size_t)b * Cc * Nn;
        int ty = tid >> 4;
        int tx = tid & 15;

        float acc[8][4];
#pragma unroll
        for (int i = 0; i < 8; i++)
#pragma unroll
            for (int j = 0; j < 4; j++) acc[i][j] = 0.f;

        for (int c0 = 0; c0 < Cc; c0 += GM_BK) {
            {
                int r2 = tid >> 4;
                int col = (tid & 15) * 8;
                const float* src = fb + (size_t)(c0 + r2) * Nn + n0 + col;
                float4 v0 = *(const float4*)(src);
                float4 v1 = *(const float4*)(src + 4);
                *(float4*)&sm.g.As[r2][col]     = v0;
                *(float4*)&sm.g.As[r2][col + 4] = v1;
            }
            {
                int oo  = tid >> 2;
                int kc4 = (tid & 3) * 4;
                const float* src = W + (size_t)(o0 + oo) * Cc + c0 + kc4;
                float4 v = *(const float4*)src;
                sm.g.Bs[kc4 + 0][oo] = v.x;
                sm.g.Bs[kc4 + 1][oo] = v.y;
                sm.g.Bs[kc4 + 2][oo] = v.z;
                sm.g.Bs[kc4 + 3][oo] = v.w;
            }
            __syncthreads();
#pragma unroll
            for (int kc = 0; kc < GM_BK; kc++) {
                float a[8], bb[4];
#pragma unroll
                for (int i = 0; i < 8; i++) a[i] = sm.g.As[kc][ty * 8 + i];
#pragma unroll
                for (int j = 0; j < 4; j++) bb[j] = sm.g.Bs[kc][tx * 4 + j];
#pragma unroll
                for (int i = 0; i < 8; i++)
#pragma unroll
                    for (int j = 0; j < 4; j++)
                        acc[i][j] = fmaf(a[i], bb[j], acc[i][j]);
            }
            __syncthreads();
        }

        float* ob = out + (size_t)b * Nn * Cc;
        float4 bv4 = *(const float4*)(bias + o0 + tx * 4);
#pragma unroll
        for (int i = 0; i < 8; i++) {
            int n = n0 + ty * 8 + i;
            float4 r2;
            r2.x = fmaxf(acc[i][0] + bv4.x, 0.f);
            r2.y = fmaxf(acc[i][1] + bv4.y, 0.f);
            r2.z = fmaxf(acc[i][2] + bv4.z, 0.f);
            r2.w = fmaxf(acc[i][3] + bv4.w, 0.f);
            *(float4*)&ob[(size_t)n * Cc + o0 + tx * 4] = r2;
        }
    }
}

// ============================================================
// KNN merge (unchanged)
// ============================================================
#define KNN_TPB 128

__global__ __launch_bounds__(KNN_TPB) void knn_merge_kernel()
{
    int b = blockIdx.y;
    int n = blockIdx.x * KNN_TPB + threadIdx.x;

    float bd[Kk];
    int   bi[Kk];
#pragma unroll
    for (int i = 0; i < Kk; i++) { bd[i] = 3.4e38f; bi[i] = 0; }

    size_t base = ((size_t)(b * Nn) + n) * NR * Kk;
    for (int e = 0; e < NR * Kk; e++) {
        float v = g_pd[base + e];
        int  ii = g_pi[base + e];
        if (v < bd[Kk - 1]) {
#pragma unroll
            for (int i = 0; i < Kk; i++) {
                if (v < bd[i]) {
                    float tv = bd[i]; int ti = bi[i];
                    bd[i] = v; bi[i] = ii;
                    v = tv; ii = ti;
                }
            }
        }
    }

    int* op = g_idx + ((size_t)(b * Nn) + n) * Kk;
#pragma unroll
    for (int i = 0; i < Kk; i++) op[i] = bi[i];
}

// ============================================================
// prep: pr (verbatim expressions) then packed {xk+pr, xv+pr}
// ============================================================
__global__ __launch_bounds__(256) void prep_kernel(
    const float* __restrict__ xyz,
    const float* __restrict__ Wp1, const float* __restrict__ bp1,
    const float* __restrict__ g1,  const float* __restrict__ b1,
    const float* __restrict__ Wp2, const float* __restrict__ bp2)
{
    int bm = blockIdx.x;
    int c = threadIdx.x;
    const float* p = xyz + (size_t)bm * 3;
    float p0 = p[0], p1v = p[1], p2 = p[2];
    float t[3];
#pragma unroll
    for (int o = 0; o < 3; o++) {
        float u = Wp1[o * 3 + 0] * p0 + Wp1[o * 3 + 1] * p1v
                + Wp1[o * 3 + 2] * p2 + bp1[o];
        u = u * (g1[o] * BN_INV) + b1[o];
        t[o] = fmaxf(u, 0.f);
    }
    float wp20 = Wp2[c * 3 + 0], wp21 = Wp2[c * 3 + 1], wp22 = Wp2[c * 3 + 2];
    float pr = fmaxf(wp20 * t[0] + wp21 * t[1] + wp22 * t[2] + bp2[c], 0.f);
    size_t base = (size_t)bm * Cc + c;
    g_kv2[base] = make_float2(g_k[base] + pr, g_v[base] + pr);
}

// ============================================================
// fused attention: 1 packed gather; phase 3 = R11-proven layout
// (warp = 4 d over full 256 c); coalesced output store
// ============================================================
__global__ __launch_bounds__(256, 3) void fused_kernel(
    const float* __restrict__ g0,  const float* __restrict__ b0,
    const float* __restrict__ Ww1, const float* __restrict__ bw1,
    const float* __restrict__ g2,  const float* __restrict__ b2,
    const float* __restrict__ Ww2, const float* __restrict__ bw2)
{
    int bx = blockIdx.x;
    int b = bx >> 13;
    int n = bx & (Nn - 1);
    int tid = threadIdx.x;
    int c = tid;
    int warp = tid >> 5;
    int lane = tid & 31;

    __shared__ __align__(16) float wv_s[Kk][Cc];
    __shared__ float w1_all[Kk][Dd];
    __shared__ float w_s[Kk][Dd];
    __shared__ float w2t_s[Dd * Dd];
    __shared__ int   idx_s[Kk];

    for (int i = tid; i < Dd * Dd; i += 256)
        w2t_s[i] = Ww2[(i & 31) * Dd + (i >> 5)];
    if (tid < Kk) idx_s[tid] = g_idx[((size_t)(b * Nn) + n) * Kk + tid];

    float xqc = g_q[((size_t)(b * Nn) + n) * Cc + c];
    float s0c = g0[c] * BN_INV, h0c = b0[c];
    float bw2r = bw2[tid & 31];

    // R11-proven phase-3 weights: warp handles d = 4*warp..4*warp+3
    // (8 warps x 4 d = 32 d: full coverage)
    float w4[4][8];
#pragma unroll
    for (int i = 0; i < 4; i++) {
        const float* wr = Ww1 + (size_t)(4 * warp + i) * Cc + 4 * lane;
        float4 t0 = *(const float4*)(wr);
        float4 t1 = *(const float4*)(wr + 128);
        w4[i][0] = t0.x; w4[i][1] = t0.y; w4[i][2] = t0.z; w4[i][3] = t0.w;
        w4[i][4] = t1.x; w4[i][5] = t1.y; w4[i][6] = t1.z; w4[i][7] = t1.w;
    }
    int d_l = 4 * warp + (lane & 3);
    float bw1_l = bw1[d_l];
    float s2_l  = g2[d_l] * BN_INV;
    float h2_l  = b2[d_l];

    __syncthreads();

    // phase 2: single packed gather per neighbor
    float vreg[Kk];
#pragma unroll 4
    for (int kk = 0; kk < Kk; kk++) {
        int m = idx_s[kk];
        float2 kv = g_kv2[((size_t)(b * Nn) + m) * Cc + c];
        wv_s[kk][c] = fmaxf((kv.x - xqc) * s0c + h0c, 0.f);
        vreg[kk] = kv.y;
    }
    __syncthreads();

    // phase 3: w1 GEMV, R=4 d per warp over full c (R11-proven)
#pragma unroll 4
    for (int kk = 0; kk < Kk; kk++) {
        const float4* wrow = (const float4*)(&wv_s[kk][0]);
        float4 v0 = wrow[lane];
        float4 v1 = wrow[lane + 32];
        float a0 = 0.f, a1 = 0.f, a2 = 0.f, a3 = 0.f;
        a0 = fmaf(w4[0][0], v0.x, a0); a0 = fmaf(w4[0][1], v0.y, a0);
        a0 = fmaf(w4[0][2], v0.z, a0); a0 = fmaf(w4[0][3], v0.w, a0);
        a0 = fmaf(w4[0][4], v1.x, a0); a0 = fmaf(w4[0][5], v1.y, a0);
        a0 = fmaf(w4[0][6], v1.z, a0); a0 = fmaf(w4[0][7], v1.w, a0);
        a1 = fmaf(w4[1][0], v0.x, a1); a1 = fmaf(w4[1][1], v0.y, a1);
        a1 = fmaf(w4[1][2], v0.z, a1); a1 = fmaf(w4[1][3], v0.w, a1);
        a1 = fmaf(w4[1][4], v1.x, a1); a1 = fmaf(w4[1][5], v1.y, a1);
        a1 = fmaf(w4[1][6], v1.z, a1); a1 = fmaf(w4[1][7], v1.w, a1);
        a2 = fmaf(w4[2][0], v0.x, a2); a2 = fmaf(w4[2][1], v0.y, a2);
        a2 = fmaf(w4[2][2], v0.z, a2); a2 = fmaf(w4[2][3], v0.w, a2);
        a2 = fmaf(w4[2][4], v1.x, a2); a2 = fmaf(w4[2][5], v1.y, a2);
        a2 = fmaf(w4[2][6], v1.z, a2); a2 = fmaf(w4[2][7], v1.w, a2);
        a3 = fmaf(w4[3][0], v0.x, a3); a3 = fmaf(w4[3][1], v0.y, a3);
        a3 = fmaf(w4[3][2], v0.z, a3); a3 = fmaf(w4[3][3], v0.w, a3);
        a3 = fmaf(w4[3][4], v1.x, a3); a3 = fmaf(w4[3][5], v1.y, a3);
        a3 = fmaf(w4[3][6], v1.z, a3); a3 = fmaf(w4[3][7], v1.w, a3);
#pragma unroll
        for (int off = 16; off > 0; off >>= 1) {
            a0 += __shfl_xor_sync(0xffffffffu, a0, off);
            a1 += __shfl_xor_sync(0xffffffffu, a1, off);
            a2 += __shfl_xor_sync(0xffffffffu, a2, off);
            a3 += __shfl_xor_sync(0xffffffffu, a3, off);
        }
        if (lane < 4) {
            float t01 = (lane & 1) ? a1 : a0;
            float t23 = (lane & 1) ? a3 : a2;
            float part = (lane & 2) ? t23 : t01;
            float u = (part + bw1_l) * s2_l + h2_l;
            w1_all[kk][4 * warp + lane] = fmaxf(u, 0.f);
        }
    }
    __syncthreads();

    // phase 4: w2
#pragma unroll
    for (int r2 = 0; r2 < 2; r2++) {
        int oidx = tid + r2 * 256;
        int k = oidx >> 5, e = oidx & 31;
        float acc = bw2r;
#pragma unroll
        for (int dd = 0; dd < Dd; dd++)
            acc = fmaf(w2t_s[dd * Dd + e], w1_all[k][dd], acc);
        w_s[k][e] = fmaxf(acc, 0.f);
    }
    __syncthreads();

    // softmax over K
    if (tid < Dd) {
        float mx = -3.4e38f;
#pragma unroll
        for (int kk = 0; kk < Kk; kk++) mx = fmaxf(mx, w_s[kk][tid]);
        float sum = 0.f;
#pragma unroll
        for (int kk = 0; kk < Kk; kk++) {
            float e = expf(w_s[kk][tid] - mx);
            w_s[kk][tid] = e;
            sum += e;
        }
        float rs = 1.0f / sum;
#pragma unroll
        for (int kk = 0; kk < Kk; kk++) w_s[kk][tid] *= rs;
    }
    __syncthreads();

    // weighted neighbor reduction; coalesced store to [b][n][c]
    float acc = 0.f;
    int dd = c & 31;
#pragma unroll
    for (int kk = 0; kk < Kk; kk++)
        acc = fmaf(vreg[kk], w_s[kk][dd], acc);
    g_tmp[((size_t)(b * Nn) + n) * Cc + c] = acc;
}

// ============================================================
// transpose: g_tmp [b][n][c] -> out [b][c][n]
// ============================================================
__global__ __launch_bounds__(256) void transpose_kernel(float* __restrict__ out)
{
    __shared__ float tile[32][33];
    int b  = blockIdx.z;
    int n0 = blockIdx.x * 32;
    int c0 = blockIdx.y * 32;
    int tx = threadIdx.x & 31;
    int ty = threadIdx.x >> 5;   // 0..7

#pragma unroll
    for (int i = 0; i < 4; i++) {
        int nn = ty + i * 8;
        tile[nn][tx] = g_tmp[((size_t)b * Nn + n0 + nn) * Cc + c0 + tx];
    }
    __syncthreads();
#pragma unroll
    for (int i = 0; i < 4; i++) {
        int cc = ty + i * 8;
        out[((size_t)b * Cc + c0 + cc) * Nn + n0 + tx] = tile[tx][cc];
    }
}

// ============================================================
// launch: super(2), merge(3), prep(4), fused(5), transpose(6)
// ============================================================
extern "C" void kernel_launch(void* const* d_in, const int* in_sizes, int n_in,
                              void* d_out, int out_size)
{
    const float* xyz  = (const float*)d_in[0];
    const float* feat = (const float*)d_in[1];
    const float* Wq = (const float*)d_in[2];   const float* bqp = (const float*)d_in[3];
    const float* Wk = (const float*)d_in[4];   const float* bkp = (const float*)d_in[5];
    const float* Wv = (const float*)d_in[6];   const float* bvp = (const float*)d_in[7];
    const float* Wp1 = (const float*)d_in[8];  const float* bp1 = (const float*)d_in[9];
    const float* g1  = (const float*)d_in[10]; const float* b1  = (const float*)d_in[11];
    const float* Wp2 = (const float*)d_in[12]; const float* bp2 = (const float*)d_in[13];
    const float* g0  = (const float*)d_in[14]; const float* b0  = (const float*)d_in[15];
    const float* Ww1 = (const float*)d_in[16]; const float* bw1 = (const float*)d_in[17];
    const float* g2  = (const float*)d_in[18]; const float* b2  = (const float*)d_in[19];
    const float* Ww2 = (const float*)d_in[20]; const float* bw2 = (const float*)d_in[21];
    float* out = (float*)d_out;

    super_kernel<<<KNN_NBLK + 3 * QKV_NBLK, 256>>>(feat, xyz,
                                                   Wq, bqp, Wk, bkp, Wv, bvp);

    dim3 mgrid(Nn / KNN_TPB, Bq);
    knn_merge_kernel<<<mgrid, KNN_TPB>>>();

    prep_kernel<<<Bq * Nn, 256>>>(xyz, Wp1, bp1, g1, b1, Wp2, bp2);

    fused_kernel<<<Bq * Nn, 256>>>(g0, b0, Ww1, bw1, g2, b2, Ww2, bw2);

    dim3 tgrid(Nn / 32, Cc / 32, Bq);
    transpose_kernel<<<tgrid, 256>>>(out);
}